// round 2
// baseline (speedup 1.0000x reference)
#include <cuda_runtime.h>
#include <cuda_bf16.h>

#define NTOK 8192
#define DIN  512
#define DH   2048
#define DOUT 512
#define NE   8

// Scratch (allocation-free rule: __device__ globals)
__device__ int   g_cnt[NE];
__device__ int   g_off[NE];
__device__ int   g_pos[NE];
__device__ int   g_idx[NTOK];
__device__ float g_h[(size_t)NTOK * DH];   // 64 MB intermediate

__global__ void k_init() {
    int t = threadIdx.x;
    if (t < NE) { g_cnt[t] = 0; g_pos[t] = 0; }
}

__global__ void k_hist(const int* __restrict__ groups) {
    int i = blockIdx.x * blockDim.x + threadIdx.x;
    if (i < NTOK) atomicAdd(&g_cnt[groups[i] & (NE - 1)], 1);
}

__global__ void k_scan() {
    int s = 0;
    for (int e = 0; e < NE; e++) { g_off[e] = s; s += g_cnt[e]; }
}

__global__ void k_scatter(const int* __restrict__ groups) {
    int i = blockIdx.x * blockDim.x + threadIdx.x;
    if (i < NTOK) {
        int e = groups[i] & (NE - 1);
        int p = atomicAdd(&g_pos[e], 1);
        g_idx[g_off[e] + p] = i;
    }
}

// PHASE 1: h = relu(x_gathered @ W1[e] + b1[e])   (K=DIN, N=DH)
// PHASE 2: out_scattered = h @ W2[e] + b2[e]      (K=DH,  N=DOUT)
template<int PHASE>
__global__ __launch_bounds__(256)
void gemm_kernel(const float* __restrict__ X,
                 const float* __restrict__ W,
                 const float* __restrict__ bias,
                 float* __restrict__ OUT)
{
    constexpr int BM = 128, BN = 128, BK = 8;
    constexpr int K = (PHASE == 1) ? DIN : DH;
    constexpr int N = (PHASE == 1) ? DH  : DOUT;
    constexpr int TPE = (NTOK + BM - 1) / BM;   // 64 m-tile slots per expert

    const int e  = blockIdx.y / TPE;
    const int mt = blockIdx.y % TPE;
    const int cnt = g_cnt[e];
    const int m0  = mt * BM;
    if (m0 >= cnt) return;
    const int off = g_off[e];
    const int bn  = blockIdx.x * BN;

    __shared__ float As[BK][BM];
    __shared__ float Bs[BK][BN];

    const float* Wb = W    + (size_t)e * K * N;
    const float* bb = bias + (size_t)e * N;

    const int tid = threadIdx.x;
    // A tile load mapping: 128 rows x 8 k, float4 per thread (2 threads/row)
    const int a_row = tid >> 1;
    const int a_k   = (tid & 1) * 4;
    // B tile load mapping: 8 k x 128 n, float4 per thread
    const int b_k = tid >> 5;
    const int b_n = (tid & 31) * 4;

    const bool a_valid = (m0 + a_row) < cnt;
    const float* Arow;
    if (PHASE == 1) {
        int tok = a_valid ? g_idx[off + m0 + a_row] : 0;
        Arow = X + (size_t)tok * K;
    } else {
        int sr = off + m0 + (a_valid ? a_row : 0);
        Arow = g_h + (size_t)sr * K;
    }

    const int ty = tid >> 4, tx = tid & 15;

    float acc[8][8];
    #pragma unroll
    for (int i = 0; i < 8; i++)
        #pragma unroll
        for (int j = 0; j < 8; j++) acc[i][j] = 0.f;

    for (int k0 = 0; k0 < K; k0 += BK) {
        float4 av = a_valid ? *(const float4*)(Arow + k0 + a_k)
                            : make_float4(0.f, 0.f, 0.f, 0.f);
        As[a_k + 0][a_row] = av.x;
        As[a_k + 1][a_row] = av.y;
        As[a_k + 2][a_row] = av.z;
        As[a_k + 3][a_row] = av.w;

        float4 bv = *(const float4*)(Wb + (size_t)(k0 + b_k) * N + bn + b_n);
        *(float4*)&Bs[b_k][b_n] = bv;

        __syncthreads();

        #pragma unroll
        for (int k = 0; k < BK; k++) {
            float ar[8], br[8];
            *(float4*)&ar[0] = *(const float4*)&As[k][ty * 8 + 0];
            *(float4*)&ar[4] = *(const float4*)&As[k][ty * 8 + 4];
            *(float4*)&br[0] = *(const float4*)&Bs[k][tx * 8 + 0];
            *(float4*)&br[4] = *(const float4*)&Bs[k][tx * 8 + 4];
            #pragma unroll
            for (int i = 0; i < 8; i++)
                #pragma unroll
                for (int j = 0; j < 8; j++)
                    acc[i][j] += ar[i] * br[j];
        }
        __syncthreads();
    }

    // Epilogue: bias (+ relu for phase 1), store
    #pragma unroll
    for (int i = 0; i < 8; i++) {
        int lr = ty * 8 + i;
        if (m0 + lr < cnt) {
            int srow = off + m0 + lr;
            float* dst;
            if (PHASE == 1) dst = g_h + (size_t)srow * N + bn;
            else            dst = OUT + (size_t)g_idx[srow] * N + bn;
            #pragma unroll
            for (int j = 0; j < 8; j += 4) {
                float4 v;
                v.x = acc[i][j + 0] + bb[bn + tx * 8 + j + 0];
                v.y = acc[i][j + 1] + bb[bn + tx * 8 + j + 1];
                v.z = acc[i][j + 2] + bb[bn + tx * 8 + j + 2];
                v.w = acc[i][j + 3] + bb[bn + tx * 8 + j + 3];
                if (PHASE == 1) {
                    v.x = fmaxf(v.x, 0.f); v.y = fmaxf(v.y, 0.f);
                    v.z = fmaxf(v.z, 0.f); v.w = fmaxf(v.w, 0.f);
                }
                *(float4*)(dst + tx * 8 + j) = v;
            }
        }
    }
}

extern "C" void kernel_launch(void* const* d_in, const int* in_sizes, int n_in,
                              void* d_out, int out_size) {
    const float* x      = (const float*)d_in[0];
    const int*   groups = (const int*)d_in[1];   // int32 (JAX demotes int64)
    const float* W1     = (const float*)d_in[2];
    const float* b1     = (const float*)d_in[3];
    const float* W2     = (const float*)d_in[4];
    const float* b2     = (const float*)d_in[5];
    float* out = (float*)d_out;

    k_init<<<1, 32>>>();
    k_hist<<<(NTOK + 255) / 256, 256>>>(groups);
    k_scan<<<1, 1>>>();
    k_scatter<<<(NTOK + 255) / 256, 256>>>(groups);

    constexpr int TPE = (NTOK + 127) / 128;  // 64
    dim3 g1(DH / 128, NE * TPE);             // 16 x 512
    dim3 g2(DOUT / 128, NE * TPE);           // 4 x 512
    gemm_kernel<1><<<g1, 256>>>(x, W1, b1, nullptr);
    gemm_kernel<2><<<g2, 256>>>(nullptr, W2, b2, out);
}

// round 4
// speedup vs baseline: 2.5446x; 2.5446x over previous
#include <cuda_runtime.h>
#include <cuda_fp16.h>
#include <cstdint>

#define NTOK 8192
#define DIN  512
#define DH   2048
#define DOUT 512
#define NE   8
#define TPE  64   // max m-tiles (128 rows) per expert

// tcgen05 is an arch-SPECIFIC (sm_103a) feature. The harness also runs a
// compute_103 (family) PTX pass where those instructions are illegal, so gate
// on the feature macro; the stub pass never executes (sm_103a SASS is used).
#if defined(__CUDA_ARCH__) && (__CUDA_ARCH__ >= 1000) && \
    (defined(__CUDA_ARCH_FEAT_SM103_ALL) || defined(__CUDA_ARCH_FEAT_SM100_ALL))
#define TC_OK 1
#else
#define TC_OK 0
#endif

// ---- scratch (__device__ globals: allocation-free rule) ----
__device__ int g_cnt[NE], g_off[NE], g_pos[NE], g_idx[NTOK];
__device__ __half g_h_hi[(size_t)NTOK * DH];   // 32 MB
__device__ __half g_h_lo[(size_t)NTOK * DH];   // 32 MB

// ================= PTX helpers (sm_103a tcgen05) =================
__device__ __forceinline__ uint32_t smem_u32(const void* p) {
    uint32_t a;
    asm("{ .reg .u64 t; cvta.to.shared.u64 t, %1; cvt.u32.u64 %0, t; }"
        : "=r"(a) : "l"(p));
    return a;
}
__device__ __forceinline__ uint32_t elect1() {
    uint32_t p;
    asm volatile("{\n\t.reg .pred p;\n\telect.sync _|p, 0xFFFFFFFF;\n\t"
                 "selp.b32 %0,1,0,p;\n\t}" : "=r"(p));
    return p;
}
#define SWZ(o) ((o) ^ (((o) >> 3) & 0x70))

static constexpr uint64_t DESC_BASE =
    (uint64_t(2) << 61) | (uint64_t(1) << 46) | (uint64_t(64) << 32) | (uint64_t(1) << 16);
__device__ __forceinline__ uint64_t mkdesc(uint32_t addr) {
    return DESC_BASE | ((uint64_t)(addr >> 4) & 0x3FFF);
}

// idesc kind::f16: dtype=F32(1)<<4, atype=F16(0), btype=F16(0), N/8<<17, M/16<<24
#define MMA_IDESC 0x08200010u  // M=128, N=128, f16 x f16 -> f32

#if TC_OK
__device__ __forceinline__ void mma_ss(uint32_t d, uint64_t a, uint64_t b, bool acc) {
    uint32_t en = acc ? 1u : 0u;
    asm volatile(
        "{\n\t.reg .pred p;\n\tsetp.ne.u32 p, %4, 0;\n\t"
        "tcgen05.mma.cta_group::1.kind::f16 [%0], %1, %2, %3, {%5,%5,%5,%5}, p;\n\t}"
        :: "r"(d), "l"(a), "l"(b), "r"(MMA_IDESC), "r"(en), "r"(0u) : "memory");
}

#define WAIT_PARITY(mbar, ph) do {                                              \
    uint32_t _m = (mbar), _p = (ph), _d;                                        \
    asm volatile("{\n\t.reg .pred p;\n\t"                                       \
        "mbarrier.try_wait.parity.acquire.cta.shared::cta.b64 p, [%1], %2;\n\t" \
        "selp.b32 %0,1,0,p;\n\t}" : "=r"(_d) : "r"(_m), "r"(_p) : "memory");    \
    if (!_d) {                                                                  \
        asm volatile("{\n\t.reg .pred P1;\n\t"                                  \
            "WL_%=:\n\t"                                                        \
            "mbarrier.try_wait.parity.acquire.cta.shared::cta.b64 P1, [%0], %1, 0x989680;\n\t" \
            "@P1 bra.uni WD_%=;\n\tbra.uni WL_%=;\n\tWD_%=:\n\t}"               \
            :: "r"(_m), "r"(_p) : "memory");                                    \
    }                                                                           \
} while (0)

#define LDTM_X32(r, ta)                                                          \
    asm volatile("tcgen05.ld.sync.aligned.32x32b.x32.b32 "                       \
        "{%0,%1,%2,%3,%4,%5,%6,%7,%8,%9,%10,%11,%12,%13,%14,%15,"                \
        "%16,%17,%18,%19,%20,%21,%22,%23,%24,%25,%26,%27,%28,%29,%30,%31}, [%32];" \
        : "=r"((r)[0]),"=r"((r)[1]),"=r"((r)[2]),"=r"((r)[3]),                   \
          "=r"((r)[4]),"=r"((r)[5]),"=r"((r)[6]),"=r"((r)[7]),                   \
          "=r"((r)[8]),"=r"((r)[9]),"=r"((r)[10]),"=r"((r)[11]),                 \
          "=r"((r)[12]),"=r"((r)[13]),"=r"((r)[14]),"=r"((r)[15]),               \
          "=r"((r)[16]),"=r"((r)[17]),"=r"((r)[18]),"=r"((r)[19]),               \
          "=r"((r)[20]),"=r"((r)[21]),"=r"((r)[22]),"=r"((r)[23]),               \
          "=r"((r)[24]),"=r"((r)[25]),"=r"((r)[26]),"=r"((r)[27]),               \
          "=r"((r)[28]),"=r"((r)[29]),"=r"((r)[30]),"=r"((r)[31])                \
        : "r"(ta))
#endif // TC_OK

__device__ __forceinline__ uint32_t pack2(__half a, __half b) {
    __half2 p = __halves2half2(a, b);
    return *reinterpret_cast<uint32_t*>(&p);
}
__device__ __forceinline__ void split(float v, __half& h, __half& l) {
    h = __float2half_rn(v);
    l = __float2half_rn(v - __half2float(h));
}

// ================= routing =================
__global__ void k_init() { int t = threadIdx.x; if (t < NE) { g_cnt[t] = 0; g_pos[t] = 0; } }
__global__ void k_hist(const int* __restrict__ g) {
    int i = blockIdx.x * blockDim.x + threadIdx.x;
    if (i < NTOK) atomicAdd(&g_cnt[g[i] & (NE - 1)], 1);
}
__global__ void k_scan() { int s = 0; for (int e = 0; e < NE; e++) { g_off[e] = s; s += g_cnt[e]; } }
__global__ void k_scatter(const int* __restrict__ g) {
    int i = blockIdx.x * blockDim.x + threadIdx.x;
    if (i < NTOK) {
        int e = g[i] & (NE - 1);
        int p = atomicAdd(&g_pos[e], 1);
        g_idx[g_off[e] + p] = i;
    }
}

// ================= tcgen05 fp16-split GEMM =================
// PHASE 1: h = relu(x_g @ W1[e] + b1[e])  K=512,  N=2048, epilogue -> fp16 hi/lo
// PHASE 2: out = h @ W2[e] + b2[e]        K=2048, N=512,  epilogue -> scatter fp32
template<int PHASE>
__global__ void __launch_bounds__(128)
gemm_tc(const float* __restrict__ X, const float* __restrict__ W,
        const float* __restrict__ bias, float* __restrict__ OUT)
{
#if TC_OK
    constexpr int K = (PHASE == 1) ? DIN : DH;
    constexpr int N = (PHASE == 1) ? DH : DOUT;
    constexpr int NCHUNK = K / 64;

    const int e  = blockIdx.y / TPE;
    const int mt = blockIdx.y % TPE;
    const int cnt = g_cnt[e];
    const int m0  = mt * 128;
    if (m0 >= cnt) return;
    const int off = g_off[e];
    const int bn  = blockIdx.x * 128;

    extern __shared__ char smem[];
    const uint32_t sb = smem_u32(smem);
    constexpr uint32_t TM_PTR = 0, MBAR = 8;
    constexpr uint32_t AHI = 1024, ALO = 1024 + 16384, BHI = 1024 + 32768, BLO = 1024 + 49152;

    const int tid = threadIdx.x, wid = tid >> 5;

    if (wid == 0) {
        asm volatile("tcgen05.alloc.cta_group::1.sync.aligned.shared::cta.b32 [%0], %1;"
                     :: "r"(sb + TM_PTR), "r"(128u) : "memory");
        asm volatile("tcgen05.relinquish_alloc_permit.cta_group::1.sync.aligned;");
    }
    __syncthreads();
    uint32_t tmem;
    asm volatile("ld.shared.b32 %0,[%1];" : "=r"(tmem) : "r"(sb + TM_PTR));
    if (tid == 0)
        asm volatile("mbarrier.init.shared.b64 [%0], %1;" :: "r"(sb + MBAR), "r"(1u) : "memory");
    __syncthreads();

    // A source pointer: thread tid owns row tid of the 128-row tile
    const float* aptr = nullptr;       // phase 1
    const __half *hhp = nullptr, *hlp = nullptr;  // phase 2
    if (PHASE == 1) {
        int r = m0 + tid;
        int tok = (r < cnt) ? g_idx[off + r] : g_idx[off];
        aptr = X + (size_t)tok * DIN;
    } else {
        int sr = off + m0 + tid; if (sr > NTOK - 1) sr = NTOK - 1;
        hhp = g_h_hi + (size_t)sr * DH;
        hlp = g_h_lo + (size_t)sr * DH;
    }
    const float* Wb = W + (size_t)e * K * N;
    const float* bb = bias + (size_t)e * N;

    const uint64_t dAhi = mkdesc(sb + AHI), dAlo = mkdesc(sb + ALO);
    const uint64_t dBhi = mkdesc(sb + BHI), dBlo = mkdesc(sb + BLO);

    int phase = 0;
    for (int kc = 0; kc < NCHUNK; kc++) {
        // ---- A tile: 128 rows x 64 k (fp16 hi/lo), 128 B/row, SW128 ----
        if (PHASE == 1) {
            const float4* ap = (const float4*)(aptr + kc * 64);
            #pragma unroll
            for (int i = 0; i < 16; i++) {
                float4 v = ap[i];
                __half h0,h1,h2,h3,l0,l1,l2,l3;
                split(v.x,h0,l0); split(v.y,h1,l1); split(v.z,h2,l2); split(v.w,h3,l3);
                uint32_t o = (uint32_t)tid * 128 + i * 8;
                uint2 uh = make_uint2(pack2(h0,h1), pack2(h2,h3));
                uint2 ul = make_uint2(pack2(l0,l1), pack2(l2,l3));
                *(uint2*)(smem + AHI + SWZ(o)) = uh;
                *(uint2*)(smem + ALO + SWZ(o)) = ul;
            }
        } else {
            const uint4* hp = (const uint4*)(hhp + kc * 64);
            const uint4* lp = (const uint4*)(hlp + kc * 64);
            #pragma unroll
            for (int i = 0; i < 8; i++) {
                uint32_t o = (uint32_t)tid * 128 + i * 16;
                *(uint4*)(smem + AHI + SWZ(o)) = hp[i];
                *(uint4*)(smem + ALO + SWZ(o)) = lp[i];
            }
        }
        // ---- B tile: W[kc*64 .. +64][bn .. +128] transposed -> [n][k] fp16 hi/lo ----
        #pragma unroll
        for (int i = 0; i < 2; i++) {
            int it = i * 128 + tid;       // 0..255
            int k8 = it >> 5;             // k-group of 8 (0..7)
            int n4 = (it & 31) * 4;       // n base (0..124)
            const float* wp = Wb + (size_t)(kc * 64 + k8 * 8) * N + bn + n4;
            float4 w[8];
            #pragma unroll
            for (int j = 0; j < 8; j++) w[j] = *(const float4*)(wp + (size_t)j * N);
            #pragma unroll
            for (int c = 0; c < 4; c++) {
                __half hh[8], ll[8];
                #pragma unroll
                for (int j = 0; j < 8; j++) {
                    float f = (&w[j].x)[c];
                    split(f, hh[j], ll[j]);
                }
                uint32_t o = (uint32_t)(n4 + c) * 128 + k8 * 16;
                uint4 uh = make_uint4(pack2(hh[0],hh[1]), pack2(hh[2],hh[3]),
                                      pack2(hh[4],hh[5]), pack2(hh[6],hh[7]));
                uint4 ul = make_uint4(pack2(ll[0],ll[1]), pack2(ll[2],ll[3]),
                                      pack2(ll[4],ll[5]), pack2(ll[6],ll[7]));
                *(uint4*)(smem + BHI + SWZ(o)) = uh;
                *(uint4*)(smem + BLO + SWZ(o)) = ul;
            }
        }
        __syncthreads();

        // ---- MMA: 4 k-steps (K=16 each) x 3 split terms ----
        if (wid == 0 && elect1()) {
            asm volatile("fence.proxy.async.shared::cta;" ::: "memory");
            #pragma unroll
            for (int s = 0; s < 4; s++) {
                uint64_t oa = (uint64_t)(s * 2);
                mma_ss(tmem, dAhi + oa, dBhi + oa, !(kc == 0 && s == 0));
                mma_ss(tmem, dAhi + oa, dBlo + oa, true);
                mma_ss(tmem, dAlo + oa, dBhi + oa, true);
            }
            asm volatile(
                "tcgen05.commit.cta_group::1.mbarrier::arrive::one.shared::cluster.b64 [%0];"
                :: "r"(sb + MBAR) : "memory");
        }
        WAIT_PARITY(sb + MBAR, phase);
        phase ^= 1;
    }

    asm volatile("tcgen05.fence::after_thread_sync;" ::: "memory");

    // ---- epilogue: D row for this thread is row (tid) via warp subpartitions ----
    const bool valid = (m0 + tid) < cnt;
    const int srow = off + m0 + tid;
    #pragma unroll
    for (int cb = 0; cb < 4; cb++) {
        uint32_t d[32];
        LDTM_X32(d, tmem + cb * 32);
        asm volatile("tcgen05.wait::ld.sync.aligned;" ::: "memory");
        if (valid) {
            int n0 = bn + cb * 32;
            if (PHASE == 1) {
                #pragma unroll
                for (int c = 0; c < 32; c += 2) {
                    float v0 = fmaxf(__uint_as_float(d[c])   + __ldg(bb + n0 + c),     0.f);
                    float v1 = fmaxf(__uint_as_float(d[c+1]) + __ldg(bb + n0 + c + 1), 0.f);
                    __half h0,h1,l0,l1;
                    split(v0,h0,l0); split(v1,h1,l1);
                    *(uint32_t*)(g_h_hi + (size_t)srow * DH + n0 + c) = pack2(h0,h1);
                    *(uint32_t*)(g_h_lo + (size_t)srow * DH + n0 + c) = pack2(l0,l1);
                }
            } else {
                int otok = g_idx[srow];
                #pragma unroll
                for (int c = 0; c < 32; c += 4) {
                    float4 v;
                    v.x = __uint_as_float(d[c])   + __ldg(bb + n0 + c);
                    v.y = __uint_as_float(d[c+1]) + __ldg(bb + n0 + c + 1);
                    v.z = __uint_as_float(d[c+2]) + __ldg(bb + n0 + c + 2);
                    v.w = __uint_as_float(d[c+3]) + __ldg(bb + n0 + c + 3);
                    *(float4*)(OUT + (size_t)otok * DOUT + n0 + c) = v;
                }
            }
        }
    }
    asm volatile("tcgen05.fence::before_thread_sync;" ::: "memory");
    __syncthreads();
    if (tid == 0)
        asm volatile("mbarrier.inval.shared.b64 [%0];" :: "r"(sb + MBAR) : "memory");
    __syncthreads();
    if (wid == 0)
        asm volatile("tcgen05.dealloc.cta_group::1.sync.aligned.b32 %0, %1;"
                     :: "r"(tmem), "r"(128u));
#endif // TC_OK
}

extern "C" void kernel_launch(void* const* d_in, const int* in_sizes, int n_in,
                              void* d_out, int out_size) {
    const float* x      = (const float*)d_in[0];
    const int*   groups = (const int*)d_in[1];   // int32 (JAX demotes int64)
    const float* W1     = (const float*)d_in[2];
    const float* b1     = (const float*)d_in[3];
    const float* W2     = (const float*)d_in[4];
    const float* b2     = (const float*)d_in[5];
    float* out = (float*)d_out;

    constexpr int SMEM_BYTES = 1024 + 4 * 16384;  // 66560
    cudaFuncSetAttribute(gemm_tc<1>, cudaFuncAttributeMaxDynamicSharedMemorySize, SMEM_BYTES);
    cudaFuncSetAttribute(gemm_tc<2>, cudaFuncAttributeMaxDynamicSharedMemorySize, SMEM_BYTES);

    k_init<<<1, 32>>>();
    k_hist<<<(NTOK + 255) / 256, 256>>>(groups);
    k_scan<<<1, 1>>>();
    k_scatter<<<(NTOK + 255) / 256, 256>>>(groups);

    gemm_tc<1><<<dim3(DH / 128,  NE * TPE), 128, SMEM_BYTES>>>(x,       W1, b1, nullptr);
    gemm_tc<2><<<dim3(DOUT / 128, NE * TPE), 128, SMEM_BYTES>>>(nullptr, W2, b2, out);
}

// round 5
// speedup vs baseline: 3.0862x; 1.2129x over previous
#include <cuda_runtime.h>
#include <cuda_fp16.h>
#include <cstdint>

#define NTOK 8192
#define DIN  512
#define DH   2048
#define DOUT 512
#define NE   8
#define TPE  64   // max m-tiles (128 rows) per expert
#define NS   3    // pipeline stages

#if defined(__CUDA_ARCH__) && (__CUDA_ARCH__ >= 1000) && \
    (defined(__CUDA_ARCH_FEAT_SM103_ALL) || defined(__CUDA_ARCH_FEAT_SM100_ALL))
#define TC_OK 1
#else
#define TC_OK 0
#endif

// ---- scratch (__device__ globals: allocation-free rule) ----
__device__ int g_cnt[NE], g_off[NE], g_pos[NE], g_idx[NTOK];
__device__ __half g_x_hi[(size_t)NTOK * DIN],  g_x_lo[(size_t)NTOK * DIN];    // sorted x
__device__ __half g_h_hi[(size_t)NTOK * DH],   g_h_lo[(size_t)NTOK * DH];     // sorted h
__device__ __half g_w1_hi[(size_t)NE * DH * DIN],  g_w1_lo[(size_t)NE * DH * DIN];   // [e][n][k]
__device__ __half g_w2_hi[(size_t)NE * DOUT * DH], g_w2_lo[(size_t)NE * DOUT * DH];  // [e][n][k]

// ================= helpers =================
__device__ __forceinline__ uint32_t smem_u32(const void* p) {
    uint32_t a;
    asm("{ .reg .u64 t; cvta.to.shared.u64 t, %1; cvt.u32.u64 %0, t; }" : "=r"(a) : "l"(p));
    return a;
}
__device__ __forceinline__ uint32_t elect1() {
    uint32_t p;
    asm volatile("{\n\t.reg .pred p;\n\telect.sync _|p, 0xFFFFFFFF;\n\t"
                 "selp.b32 %0,1,0,p;\n\t}" : "=r"(p));
    return p;
}
#define SWZ(o) ((o) ^ (((o) >> 3) & 0x70))

static constexpr uint64_t DESC_BASE =
    (uint64_t(2) << 61) | (uint64_t(1) << 46) | (uint64_t(64) << 32) | (uint64_t(1) << 16);
__device__ __forceinline__ uint64_t mkdesc(uint32_t addr) {
    return DESC_BASE | ((uint64_t)(addr >> 4) & 0x3FFF);
}

#define MMA_IDESC 0x08200010u  // kind::f16, f32 accum, M=128, N=128

__device__ __forceinline__ uint32_t pack2(__half a, __half b) {
    __half2 p = __halves2half2(a, b);
    return *reinterpret_cast<uint32_t*>(&p);
}
__device__ __forceinline__ void split(float v, __half& h, __half& l) {
    h = __float2half_rn(v);
    l = __float2half_rn(v - __half2float(h));
}

__device__ __forceinline__ void cpa16(uint32_t dst, const void* src) {
    asm volatile("cp.async.cg.shared.global [%0], [%1], 16;" :: "r"(dst), "l"(src) : "memory");
}
#define CP_COMMIT() asm volatile("cp.async.commit_group;" ::: "memory")

#if TC_OK
__device__ __forceinline__ void mma_ss(uint32_t d, uint64_t a, uint64_t b, bool acc) {
    uint32_t en = acc ? 1u : 0u;
    asm volatile(
        "{\n\t.reg .pred p;\n\tsetp.ne.u32 p, %4, 0;\n\t"
        "tcgen05.mma.cta_group::1.kind::f16 [%0], %1, %2, %3, {%5,%5,%5,%5}, p;\n\t}"
        :: "r"(d), "l"(a), "l"(b), "r"(MMA_IDESC), "r"(en), "r"(0u) : "memory");
}

#define WAIT_PARITY(mbar, ph) do {                                              \
    uint32_t _m = (mbar), _p = (ph), _d;                                        \
    asm volatile("{\n\t.reg .pred p;\n\t"                                       \
        "mbarrier.try_wait.parity.acquire.cta.shared::cta.b64 p, [%1], %2;\n\t" \
        "selp.b32 %0,1,0,p;\n\t}" : "=r"(_d) : "r"(_m), "r"(_p) : "memory");    \
    if (!_d) {                                                                  \
        asm volatile("{\n\t.reg .pred P1;\n\t"                                  \
            "WL_%=:\n\t"                                                        \
            "mbarrier.try_wait.parity.acquire.cta.shared::cta.b64 P1, [%0], %1, 0x989680;\n\t" \
            "@P1 bra.uni WD_%=;\n\tbra.uni WL_%=;\n\tWD_%=:\n\t}"               \
            :: "r"(_m), "r"(_p) : "memory");                                    \
    }                                                                           \
} while (0)

#define LDTM_X32(r, ta)                                                          \
    asm volatile("tcgen05.ld.sync.aligned.32x32b.x32.b32 "                       \
        "{%0,%1,%2,%3,%4,%5,%6,%7,%8,%9,%10,%11,%12,%13,%14,%15,"                \
        "%16,%17,%18,%19,%20,%21,%22,%23,%24,%25,%26,%27,%28,%29,%30,%31}, [%32];" \
        : "=r"((r)[0]),"=r"((r)[1]),"=r"((r)[2]),"=r"((r)[3]),                   \
          "=r"((r)[4]),"=r"((r)[5]),"=r"((r)[6]),"=r"((r)[7]),                   \
          "=r"((r)[8]),"=r"((r)[9]),"=r"((r)[10]),"=r"((r)[11]),                 \
          "=r"((r)[12]),"=r"((r)[13]),"=r"((r)[14]),"=r"((r)[15]),               \
          "=r"((r)[16]),"=r"((r)[17]),"=r"((r)[18]),"=r"((r)[19]),               \
          "=r"((r)[20]),"=r"((r)[21]),"=r"((r)[22]),"=r"((r)[23]),               \
          "=r"((r)[24]),"=r"((r)[25]),"=r"((r)[26]),"=r"((r)[27]),               \
          "=r"((r)[28]),"=r"((r)[29]),"=r"((r)[30]),"=r"((r)[31])                \
        : "r"(ta))
#endif // TC_OK

// ================= routing =================
__global__ void k_init() { int t = threadIdx.x; if (t < NE) { g_cnt[t] = 0; g_pos[t] = 0; } }
__global__ void k_hist(const int* __restrict__ g) {
    int i = blockIdx.x * blockDim.x + threadIdx.x;
    if (i < NTOK) atomicAdd(&g_cnt[g[i] & (NE - 1)], 1);
}
__global__ void k_scan() { int s = 0; for (int e = 0; e < NE; e++) { g_off[e] = s; s += g_cnt[e]; } }
__global__ void k_scatter(const int* __restrict__ g) {
    int i = blockIdx.x * blockDim.x + threadIdx.x;
    if (i < NTOK) {
        int e = g[i] & (NE - 1);
        int p = atomicAdd(&g_pos[e], 1);
        g_idx[g_off[e] + p] = i;
    }
}

// ================= pre-conversion =================
// x: gather into sorted order + fp16 hi/lo split. One thread per float4.
__global__ void __launch_bounds__(256) k_convert_x(const float* __restrict__ x) {
    int i = blockIdx.x * blockDim.x + threadIdx.x;   // 0 .. NTOK*DIN/4-1
    int row = i >> 7;                 // DIN/4 = 128 float4 per row
    int c = (i & 127) * 4;
    int tok = g_idx[row];
    float4 v = *(const float4*)(x + (size_t)tok * DIN + c);
    __half h0,h1,h2,h3,l0,l1,l2,l3;
    split(v.x,h0,l0); split(v.y,h1,l1); split(v.z,h2,l2); split(v.w,h3,l3);
    *(uint2*)(g_x_hi + (size_t)row * DIN + c) = make_uint2(pack2(h0,h1), pack2(h2,h3));
    *(uint2*)(g_x_lo + (size_t)row * DIN + c) = make_uint2(pack2(l0,l1), pack2(l2,l3));
}

// W [e][K][N] fp32 -> Wt hi/lo [e][N][K] fp16 (SMEM 32x32 tile transpose)
__global__ void __launch_bounds__(256) k_convert_w(const float* __restrict__ W,
                                                   __half* __restrict__ Whi,
                                                   __half* __restrict__ Wlo,
                                                   int K, int N) {
    __shared__ float t[32][33];
    int e = blockIdx.z;
    int k0 = blockIdx.y * 32, n0 = blockIdx.x * 32;
    int tx = threadIdx.x, ty = threadIdx.y;   // (32, 8)
    const float* Wb = W + (size_t)e * K * N;
    #pragma unroll
    for (int j = 0; j < 4; j++) {
        int kk = ty + j * 8;
        t[kk][tx] = Wb[(size_t)(k0 + kk) * N + n0 + tx];
    }
    __syncthreads();
    __half* Hb = Whi + ((size_t)e * N + n0) * K + k0;
    __half* Lb = Wlo + ((size_t)e * N + n0) * K + k0;
    #pragma unroll
    for (int j = 0; j < 4; j++) {
        int nn = ty + j * 8;
        float v = t[tx][nn];
        __half h, l; split(v, h, l);
        Hb[(size_t)nn * K + tx] = h;
        Lb[(size_t)nn * K + tx] = l;
    }
}

// ================= tcgen05 fp16-split GEMM, cp.async 3-stage =================
// PHASE 1: h = relu(x_s @ W1t^T + b1)  K=512,  N=2048
// PHASE 2: out = h_s @ W2t^T + b2      K=2048, N=512  (scatter store)
template<int PHASE>
__global__ void __launch_bounds__(128)
gemm_tc(const float* __restrict__ bias, float* __restrict__ OUT)
{
#if TC_OK
    constexpr int K = (PHASE == 1) ? DIN : DH;
    constexpr int N = (PHASE == 1) ? DH : DOUT;
    constexpr int NCHUNK = K / 64;
    constexpr uint32_t STAGE_BYTES = 65536;

    const int e  = blockIdx.y / TPE;
    const int mt = blockIdx.y % TPE;
    const int cnt = g_cnt[e];
    const int m0  = mt * 128;
    if (m0 >= cnt) return;
    const int off = g_off[e];
    const int bn  = blockIdx.x * 128;

    extern __shared__ char smem[];
    const uint32_t sb = smem_u32(smem);
    // header: [0] tmem ptr, [8,16,24] mbars; stages at 1024 + s*64K
    const int tid = threadIdx.x, wid = tid >> 5;

    if (wid == 0) {
        asm volatile("tcgen05.alloc.cta_group::1.sync.aligned.shared::cta.b32 [%0], %1;"
                     :: "r"(sb), "r"(128u) : "memory");
        asm volatile("tcgen05.relinquish_alloc_permit.cta_group::1.sync.aligned;");
    }
    __syncthreads();
    uint32_t tmem;
    asm volatile("ld.shared.b32 %0,[%1];" : "=r"(tmem) : "r"(sb));
    if (tid == 0) {
        #pragma unroll
        for (int s = 0; s < NS; s++)
            asm volatile("mbarrier.init.shared.b64 [%0], %1;" :: "r"(sb + 8 + s * 8), "r"(1u) : "memory");
    }
    __syncthreads();

    // ---- source row pointers (bytes) ----
    int sr = off + m0 + tid; if (sr > NTOK - 1) sr = NTOK - 1;
    const char *ahp, *alp, *bhp, *blp;
    if (PHASE == 1) {
        ahp = (const char*)(g_x_hi + (size_t)sr * DIN);
        alp = (const char*)(g_x_lo + (size_t)sr * DIN);
        bhp = (const char*)(g_w1_hi + ((size_t)e * DH + bn + tid) * DIN);
        blp = (const char*)(g_w1_lo + ((size_t)e * DH + bn + tid) * DIN);
    } else {
        ahp = (const char*)(g_h_hi + (size_t)sr * DH);
        alp = (const char*)(g_h_lo + (size_t)sr * DH);
        bhp = (const char*)(g_w2_hi + ((size_t)e * DOUT + bn + tid) * DH);
        blp = (const char*)(g_w2_lo + ((size_t)e * DOUT + bn + tid) * DH);
    }
    const float* bb = bias + (size_t)e * N;

    const uint32_t swz_row = SWZ((uint32_t)tid * 128);  // swizzle of row base; i*16 xor below
    // (SWZ distributes over the low 128B within row: compute per-i inside)

    // ---- issue loads for chunk kc into its stage ----
    auto issue = [&](int kc) {
        uint32_t st = sb + 1024 + (uint32_t)(kc % NS) * STAGE_BYTES;
        const char* a_h = ahp + kc * 128;
        const char* a_l = alp + kc * 128;
        const char* b_h = bhp + kc * 128;
        const char* b_l = blp + kc * 128;
        #pragma unroll
        for (int i = 0; i < 8; i++) {
            uint32_t o = SWZ((uint32_t)tid * 128 + i * 16);
            cpa16(st + 0     + o, a_h + i * 16);
            cpa16(st + 16384 + o, a_l + i * 16);
            cpa16(st + 32768 + o, b_h + i * 16);
            cpa16(st + 49152 + o, b_l + i * 16);
        }
        CP_COMMIT();
    };

    #pragma unroll
    for (int s = 0; s < NS; s++) issue(s);

    for (int kc = 0; kc < NCHUNK; kc++) {
        const int stage = kc % NS;
        // wait until loads for chunk kc are complete
        if (kc <= NCHUNK - 3)      asm volatile("cp.async.wait_group 2;" ::: "memory");
        else if (kc == NCHUNK - 2) asm volatile("cp.async.wait_group 1;" ::: "memory");
        else                       asm volatile("cp.async.wait_group 0;" ::: "memory");
        __syncthreads();

        if (wid == 0 && elect1()) {
            asm volatile("fence.proxy.async.shared::cta;" ::: "memory");
            uint32_t st = sb + 1024 + (uint32_t)stage * STAGE_BYTES;
            uint64_t dAh = mkdesc(st), dAl = mkdesc(st + 16384);
            uint64_t dBh = mkdesc(st + 32768), dBl = mkdesc(st + 49152);
            #pragma unroll
            for (int s = 0; s < 4; s++) {
                uint64_t oa = (uint64_t)(s * 2);
                mma_ss(tmem, dAh + oa, dBh + oa, !(kc == 0 && s == 0));
                mma_ss(tmem, dAh + oa, dBl + oa, true);
                mma_ss(tmem, dAl + oa, dBh + oa, true);
            }
            asm volatile(
                "tcgen05.commit.cta_group::1.mbarrier::arrive::one.shared::cluster.b64 [%0];"
                :: "r"(sb + 8 + stage * 8) : "memory");
        }

        if (kc + NS < NCHUNK) {
            WAIT_PARITY(sb + 8 + stage * 8, (kc / NS) & 1);   // MMA(kc) done -> stage reusable
            issue(kc + NS);
        }
    }
    // wait for final MMA
    WAIT_PARITY(sb + 8 + ((NCHUNK - 1) % NS) * 8, ((NCHUNK - 1) / NS) & 1);
    asm volatile("tcgen05.fence::after_thread_sync;" ::: "memory");

    // ---- epilogue ----
    const bool valid = (m0 + tid) < cnt;
    const int srow = off + m0 + tid;
    #pragma unroll
    for (int cb = 0; cb < 4; cb++) {
        uint32_t d[32];
        LDTM_X32(d, tmem + cb * 32);
        asm volatile("tcgen05.wait::ld.sync.aligned;" ::: "memory");
        if (valid) {
            int n0 = bn + cb * 32;
            if (PHASE == 1) {
                #pragma unroll
                for (int c = 0; c < 32; c += 2) {
                    float v0 = fmaxf(__uint_as_float(d[c])   + __ldg(bb + n0 + c),     0.f);
                    float v1 = fmaxf(__uint_as_float(d[c+1]) + __ldg(bb + n0 + c + 1), 0.f);
                    __half h0,h1,l0,l1;
                    split(v0,h0,l0); split(v1,h1,l1);
                    *(uint32_t*)(g_h_hi + (size_t)srow * DH + n0 + c) = pack2(h0,h1);
                    *(uint32_t*)(g_h_lo + (size_t)srow * DH + n0 + c) = pack2(l0,l1);
                }
            } else {
                int otok = g_idx[srow];
                #pragma unroll
                for (int c = 0; c < 32; c += 4) {
                    float4 v;
                    v.x = __uint_as_float(d[c])   + __ldg(bb + n0 + c);
                    v.y = __uint_as_float(d[c+1]) + __ldg(bb + n0 + c + 1);
                    v.z = __uint_as_float(d[c+2]) + __ldg(bb + n0 + c + 2);
                    v.w = __uint_as_float(d[c+3]) + __ldg(bb + n0 + c + 3);
                    *(float4*)(OUT + (size_t)otok * DOUT + n0 + c) = v;
                }
            }
        }
    }
    asm volatile("tcgen05.fence::before_thread_sync;" ::: "memory");
    __syncthreads();
    if (tid == 0) {
        #pragma unroll
        for (int s = 0; s < NS; s++)
            asm volatile("mbarrier.inval.shared.b64 [%0];" :: "r"(sb + 8 + s * 8) : "memory");
    }
    __syncthreads();
    if (wid == 0)
        asm volatile("tcgen05.dealloc.cta_group::1.sync.aligned.b32 %0, %1;"
                     :: "r"(tmem), "r"(128u));
#endif // TC_OK
}

extern "C" void kernel_launch(void* const* d_in, const int* in_sizes, int n_in,
                              void* d_out, int out_size) {
    const float* x      = (const float*)d_in[0];
    const int*   groups = (const int*)d_in[1];   // int32 (JAX demotes int64)
    const float* W1     = (const float*)d_in[2];
    const float* b1     = (const float*)d_in[3];
    const float* W2     = (const float*)d_in[4];
    const float* b2     = (const float*)d_in[5];
    float* out = (float*)d_out;

    constexpr int SMEM_BYTES = 1024 + NS * 65536;  // 197632
    cudaFuncSetAttribute(gemm_tc<1>, cudaFuncAttributeMaxDynamicSharedMemorySize, SMEM_BYTES);
    cudaFuncSetAttribute(gemm_tc<2>, cudaFuncAttributeMaxDynamicSharedMemorySize, SMEM_BYTES);

    // routing
    k_init<<<1, 32>>>();
    k_hist<<<(NTOK + 255) / 256, 256>>>(groups);
    k_scan<<<1, 1>>>();
    k_scatter<<<(NTOK + 255) / 256, 256>>>(groups);

    // pre-conversion
    __half *w1h, *w1l, *w2h, *w2l;
    cudaGetSymbolAddress((void**)&w1h, g_w1_hi);
    cudaGetSymbolAddress((void**)&w1l, g_w1_lo);
    cudaGetSymbolAddress((void**)&w2h, g_w2_hi);
    cudaGetSymbolAddress((void**)&w2l, g_w2_lo);
    k_convert_x<<<(NTOK * DIN / 4) / 256, 256>>>(x);
    k_convert_w<<<dim3(DH / 32, DIN / 32, NE), dim3(32, 8)>>>(W1, w1h, w1l, DIN, DH);
    k_convert_w<<<dim3(DOUT / 32, DH / 32, NE), dim3(32, 8)>>>(W2, w2h, w2l, DH, DOUT);

    // GEMMs
    gemm_tc<1><<<dim3(DH / 128,  NE * TPE), 128, SMEM_BYTES>>>(b1, nullptr);
    gemm_tc<2><<<dim3(DOUT / 128, NE * TPE), 128, SMEM_BYTES>>>(b2, out);
}

// round 7
// speedup vs baseline: 6.0480x; 1.9597x over previous
#include <cuda_runtime.h>
#include <cuda_fp16.h>
#include <cuda.h>
#include <cstdint>

#define NTOK 8192
#define DIN  512
#define DH   2048
#define DOUT 512
#define NE   8
#define TPE  64   // max m-tiles (128 rows) per expert
#define NS   3    // pipeline stages

#if defined(__CUDA_ARCH__) && (__CUDA_ARCH__ >= 1000) && \
    (defined(__CUDA_ARCH_FEAT_SM103_ALL) || defined(__CUDA_ARCH_FEAT_SM100_ALL))
#define TC_OK 1
#else
#define TC_OK 0
#endif

// ---- scratch (__device__ globals: allocation-free rule) ----
__device__ int g_cnt[NE], g_off[NE], g_pos[NE], g_idx[NTOK];
__device__ __half g_x_hi[(size_t)NTOK * DIN],  g_x_lo[(size_t)NTOK * DIN];    // sorted x
__device__ __half g_h_hi[(size_t)NTOK * DH],   g_h_lo[(size_t)NTOK * DH];     // sorted h
__device__ __half g_w1_hi[(size_t)NE * DH * DIN],  g_w1_lo[(size_t)NE * DH * DIN];   // [e][n][k]
__device__ __half g_w2_hi[(size_t)NE * DOUT * DH], g_w2_lo[(size_t)NE * DOUT * DH];  // [e][n][k]

// ================= helpers =================
__device__ __forceinline__ uint32_t smem_u32(const void* p) {
    uint32_t a;
    asm("{ .reg .u64 t; cvta.to.shared.u64 t, %1; cvt.u32.u64 %0, t; }" : "=r"(a) : "l"(p));
    return a;
}

static constexpr uint64_t DESC_BASE =
    (uint64_t(2) << 61) | (uint64_t(1) << 46) | (uint64_t(64) << 32) | (uint64_t(1) << 16);
__device__ __forceinline__ uint64_t mkdesc(uint32_t addr) {
    return DESC_BASE | ((uint64_t)(addr >> 4) & 0x3FFF);
}

#define MMA_IDESC 0x08200010u  // kind::f16, f32 accum, M=128, N=128

__device__ __forceinline__ uint32_t pack2(__half a, __half b) {
    __half2 p = __halves2half2(a, b);
    return *reinterpret_cast<uint32_t*>(&p);
}
__device__ __forceinline__ void split(float v, __half& h, __half& l) {
    h = __float2half_rn(v);
    l = __float2half_rn(v - __half2float(h));
}

#if TC_OK
__device__ __forceinline__ void mma_ss(uint32_t d, uint64_t a, uint64_t b, bool acc) {
    uint32_t en = acc ? 1u : 0u;
    asm volatile(
        "{\n\t.reg .pred p;\n\tsetp.ne.u32 p, %4, 0;\n\t"
        "tcgen05.mma.cta_group::1.kind::f16 [%0], %1, %2, %3, {%5,%5,%5,%5}, p;\n\t}"
        :: "r"(d), "l"(a), "l"(b), "r"(MMA_IDESC), "r"(en), "r"(0u) : "memory");
}

#define WAIT_PARITY(mbar, ph) do {                                              \
    uint32_t _m = (mbar), _p = (ph), _d;                                        \
    asm volatile("{\n\t.reg .pred p;\n\t"                                       \
        "mbarrier.try_wait.parity.acquire.cta.shared::cta.b64 p, [%1], %2;\n\t" \
        "selp.b32 %0,1,0,p;\n\t}" : "=r"(_d) : "r"(_m), "r"(_p) : "memory");    \
    if (!_d) {                                                                  \
        asm volatile("{\n\t.reg .pred P1;\n\t"                                  \
            "WL_%=:\n\t"                                                        \
            "mbarrier.try_wait.parity.acquire.cta.shared::cta.b64 P1, [%0], %1, 0x989680;\n\t" \
            "@P1 bra.uni WD_%=;\n\tbra.uni WL_%=;\n\tWD_%=:\n\t}"               \
            :: "r"(_m), "r"(_p) : "memory");                                    \
    }                                                                           \
} while (0)

#define TMA3D(smaddr, tmap, cx, cy, cz, mbar)                                      \
    asm volatile(                                                                  \
        "cp.async.bulk.tensor.3d.shared::cta.global.tile.mbarrier::complete_tx::bytes " \
        "[%0], [%1, {%2, %3, %4}], [%5];"                                          \
        :: "r"(smaddr), "l"(tmap), "r"(cx), "r"(cy), "r"(cz), "r"(mbar) : "memory")

#define LDTM_X32(r, ta)                                                          \
    asm volatile("tcgen05.ld.sync.aligned.32x32b.x32.b32 "                       \
        "{%0,%1,%2,%3,%4,%5,%6,%7,%8,%9,%10,%11,%12,%13,%14,%15,"                \
        "%16,%17,%18,%19,%20,%21,%22,%23,%24,%25,%26,%27,%28,%29,%30,%31}, [%32];" \
        : "=r"((r)[0]),"=r"((r)[1]),"=r"((r)[2]),"=r"((r)[3]),                   \
          "=r"((r)[4]),"=r"((r)[5]),"=r"((r)[6]),"=r"((r)[7]),                   \
          "=r"((r)[8]),"=r"((r)[9]),"=r"((r)[10]),"=r"((r)[11]),                 \
          "=r"((r)[12]),"=r"((r)[13]),"=r"((r)[14]),"=r"((r)[15]),               \
          "=r"((r)[16]),"=r"((r)[17]),"=r"((r)[18]),"=r"((r)[19]),               \
          "=r"((r)[20]),"=r"((r)[21]),"=r"((r)[22]),"=r"((r)[23]),               \
          "=r"((r)[24]),"=r"((r)[25]),"=r"((r)[26]),"=r"((r)[27]),               \
          "=r"((r)[28]),"=r"((r)[29]),"=r"((r)[30]),"=r"((r)[31])                \
        : "r"(ta))
#endif // TC_OK

// ================= routing (fused: 2 launches) =================
__global__ void k_count(const int* __restrict__ g) {
    __shared__ int c[NE];
    int tid = threadIdx.x;
    if (tid < NE) { c[tid] = 0; g_pos[tid] = 0; }
    __syncthreads();
    for (int i = tid; i < NTOK; i += blockDim.x) atomicAdd(&c[g[i] & (NE - 1)], 1);
    __syncthreads();
    if (tid == 0) {
        int s = 0;
        for (int e = 0; e < NE; e++) { g_off[e] = s; g_cnt[e] = c[e]; s += c[e]; }
    }
}
__global__ void k_scatter(const int* __restrict__ g) {
    int i = blockIdx.x * blockDim.x + threadIdx.x;
    if (i < NTOK) {
        int e = g[i] & (NE - 1);
        int p = atomicAdd(&g_pos[e], 1);
        g_idx[g_off[e] + p] = i;
    }
}

// ================= pre-conversion =================
__global__ void __launch_bounds__(256) k_convert_x(const float* __restrict__ x) {
    int i = blockIdx.x * blockDim.x + threadIdx.x;   // 0 .. NTOK*DIN/4-1
    int row = i >> 7;                 // DIN/4 = 128 float4 per row
    int c = (i & 127) * 4;
    int tok = g_idx[row];
    float4 v = *(const float4*)(x + (size_t)tok * DIN + c);
    __half h0,h1,h2,h3,l0,l1,l2,l3;
    split(v.x,h0,l0); split(v.y,h1,l1); split(v.z,h2,l2); split(v.w,h3,l3);
    *(uint2*)(g_x_hi + (size_t)row * DIN + c) = make_uint2(pack2(h0,h1), pack2(h2,h3));
    *(uint2*)(g_x_lo + (size_t)row * DIN + c) = make_uint2(pack2(l0,l1), pack2(l2,l3));
}

// W [e][K][N] fp32 -> Wt hi/lo [e][N][K] fp16 (SMEM 32x32 tile transpose)
__global__ void __launch_bounds__(256) k_convert_w(const float* __restrict__ W,
                                                   __half* __restrict__ Whi,
                                                   __half* __restrict__ Wlo,
                                                   int K, int N) {
    __shared__ float t[32][33];
    int e = blockIdx.z;
    int k0 = blockIdx.y * 32, n0 = blockIdx.x * 32;
    int tx = threadIdx.x, ty = threadIdx.y;   // (32, 8)
    const float* Wb = W + (size_t)e * K * N;
    #pragma unroll
    for (int j = 0; j < 4; j++) {
        int kk = ty + j * 8;
        t[kk][tx] = Wb[(size_t)(k0 + kk) * N + n0 + tx];
    }
    __syncthreads();
    __half* Hb = Whi + ((size_t)e * N + n0) * K + k0;
    __half* Lb = Wlo + ((size_t)e * N + n0) * K + k0;
    #pragma unroll
    for (int j = 0; j < 4; j++) {
        int nn = ty + j * 8;
        float v = t[tx][nn];
        __half h, l; split(v, h, l);
        Hb[(size_t)nn * K + tx] = h;
        Lb[(size_t)nn * K + tx] = l;
    }
}

// ================= tcgen05 fp16-split GEMM, TMA 3-stage producer/consumer =====
// PHASE 1: h = relu(x_s @ W1t^T + b1)  K=512,  N=2048
// PHASE 2: out = h_s @ W2t^T + b2      K=2048, N=512  (scatter store)
template<int PHASE>
__global__ void __launch_bounds__(128)
gemm_tc(const __grid_constant__ CUtensorMap tmAh,
        const __grid_constant__ CUtensorMap tmAl,
        const __grid_constant__ CUtensorMap tmBh,
        const __grid_constant__ CUtensorMap tmBl,
        const float* __restrict__ bias, float* __restrict__ OUT)
{
#if TC_OK
    constexpr int K = (PHASE == 1) ? DIN : DH;
    constexpr int N = (PHASE == 1) ? DH : DOUT;
    constexpr int NCHUNK = K / 64;
    constexpr uint32_t STAGE_BYTES = 65536;

    const int e  = blockIdx.y / TPE;
    const int mt = blockIdx.y % TPE;
    const int cnt = g_cnt[e];
    const int m0  = mt * 128;
    if (m0 >= cnt) return;
    const int off = g_off[e];
    const int bn  = blockIdx.x * 128;

    extern __shared__ char smem[];
    const uint32_t sb = smem_u32(smem);
    // header: [0] tmem ptr; full mbars at 8+8s; empty at 32+8s; done at 56
    const int tid = threadIdx.x, wid = tid >> 5;

    if (wid == 0) {
        asm volatile("tcgen05.alloc.cta_group::1.sync.aligned.shared::cta.b32 [%0], %1;"
                     :: "r"(sb), "r"(128u) : "memory");
        asm volatile("tcgen05.relinquish_alloc_permit.cta_group::1.sync.aligned;");
    }
    __syncthreads();
    uint32_t tmem;
    asm volatile("ld.shared.b32 %0,[%1];" : "=r"(tmem) : "r"(sb));
    if (tid == 0) {
        #pragma unroll
        for (int s = 0; s < NS; s++) {
            asm volatile("mbarrier.init.shared.b64 [%0], 1;" :: "r"(sb + 8  + s * 8) : "memory");
            asm volatile("mbarrier.init.shared.b64 [%0], 1;" :: "r"(sb + 32 + s * 8) : "memory");
        }
        asm volatile("mbarrier.init.shared.b64 [%0], 1;" :: "r"(sb + 56) : "memory");
    }
    __syncthreads();

    const int rowA = off + m0;   // OOB rows -> TMA zero fill

    if (tid == 96) {
        // ================= producer: TMA =================
        for (int kc = 0; kc < NCHUNK; kc++) {
            const int s = kc % NS;
            const int r = kc / NS;
            WAIT_PARITY(sb + 32 + s * 8, (r & 1) ^ 1);   // stage free (first pass immediate)
            uint32_t full = sb + 8 + s * 8;
            asm volatile("mbarrier.arrive.expect_tx.shared.b64 _, [%0], %1;"
                         :: "r"(full), "r"(STAGE_BYTES) : "memory");
            uint32_t st = sb + 1024 + (uint32_t)s * STAGE_BYTES;
            int kx = kc * 64;
            TMA3D(st + 0,     &tmAh, kx, rowA, 0, full);
            TMA3D(st + 16384, &tmAl, kx, rowA, 0, full);
            TMA3D(st + 32768, &tmBh, kx, bn,   e, full);
            TMA3D(st + 49152, &tmBl, kx, bn,   e, full);
        }
    } else if (tid == 0) {
        // ================= consumer: MMA =================
        for (int kc = 0; kc < NCHUNK; kc++) {
            const int s = kc % NS;
            const int r = kc / NS;
            WAIT_PARITY(sb + 8 + s * 8, r & 1);          // data ready
            uint32_t st = sb + 1024 + (uint32_t)s * STAGE_BYTES;
            uint64_t dAh = mkdesc(st), dAl = mkdesc(st + 16384);
            uint64_t dBh = mkdesc(st + 32768), dBl = mkdesc(st + 49152);
            #pragma unroll
            for (int ks = 0; ks < 4; ks++) {
                uint64_t oa = (uint64_t)(ks * 2);
                mma_ss(tmem, dAh + oa, dBh + oa, !(kc == 0 && ks == 0));
                mma_ss(tmem, dAh + oa, dBl + oa, true);
                mma_ss(tmem, dAl + oa, dBh + oa, true);
            }
            asm volatile(
                "tcgen05.commit.cta_group::1.mbarrier::arrive::one.shared::cluster.b64 [%0];"
                :: "r"(sb + 32 + s * 8) : "memory");
        }
        asm volatile(
            "tcgen05.commit.cta_group::1.mbarrier::arrive::one.shared::cluster.b64 [%0];"
            :: "r"(sb + 56) : "memory");
    }

    // all threads wait for the final MMA
    WAIT_PARITY(sb + 56, 0);
    asm volatile("tcgen05.fence::after_thread_sync;" ::: "memory");

    // ---- epilogue: thread tid owns output row tid of the tile ----
    const float* bb = bias + (size_t)e * N;
    const bool valid = (m0 + tid) < cnt;
    const int srow = off + m0 + tid;
    #pragma unroll
    for (int cb = 0; cb < 4; cb++) {
        uint32_t d[32];
        LDTM_X32(d, tmem + cb * 32);
        asm volatile("tcgen05.wait::ld.sync.aligned;" ::: "memory");
        if (valid) {
            int n0 = bn + cb * 32;
            if (PHASE == 1) {
                #pragma unroll
                for (int c = 0; c < 32; c += 2) {
                    float v0 = fmaxf(__uint_as_float(d[c])   + __ldg(bb + n0 + c),     0.f);
                    float v1 = fmaxf(__uint_as_float(d[c+1]) + __ldg(bb + n0 + c + 1), 0.f);
                    __half h0,h1,l0,l1;
                    split(v0,h0,l0); split(v1,h1,l1);
                    *(uint32_t*)(g_h_hi + (size_t)srow * DH + n0 + c) = pack2(h0,h1);
                    *(uint32_t*)(g_h_lo + (size_t)srow * DH + n0 + c) = pack2(l0,l1);
                }
            } else {
                int otok = g_idx[srow];
                #pragma unroll
                for (int c = 0; c < 32; c += 4) {
                    float4 v;
                    v.x = __uint_as_float(d[c])   + __ldg(bb + n0 + c);
                    v.y = __uint_as_float(d[c+1]) + __ldg(bb + n0 + c + 1);
                    v.z = __uint_as_float(d[c+2]) + __ldg(bb + n0 + c + 2);
                    v.w = __uint_as_float(d[c+3]) + __ldg(bb + n0 + c + 3);
                    *(float4*)(OUT + (size_t)otok * DOUT + n0 + c) = v;
                }
            }
        }
    }
    asm volatile("tcgen05.fence::before_thread_sync;" ::: "memory");
    __syncthreads();
    if (tid == 0) {
        #pragma unroll
        for (int s = 0; s < NS; s++) {
            asm volatile("mbarrier.inval.shared.b64 [%0];" :: "r"(sb + 8  + s * 8) : "memory");
            asm volatile("mbarrier.inval.shared.b64 [%0];" :: "r"(sb + 32 + s * 8) : "memory");
        }
        asm volatile("mbarrier.inval.shared.b64 [%0];" :: "r"(sb + 56) : "memory");
    }
    __syncthreads();
    if (wid == 0)
        asm volatile("tcgen05.dealloc.cta_group::1.sync.aligned.b32 %0, %1;"
                     :: "r"(tmem), "r"(128u));
#endif // TC_OK
}

// ================= host: tensormap builder =================
typedef CUresult (*PFN_tmEncode)(CUtensorMap*, CUtensorMapDataType, cuuint32_t, void*,
                                 const cuuint64_t*, const cuuint64_t*, const cuuint32_t*,
                                 const cuuint32_t*, CUtensorMapInterleave, CUtensorMapSwizzle,
                                 CUtensorMapL2promotion, CUtensorMapFloatOOBfill);

static void make_map(PFN_tmEncode enc, CUtensorMap* tm, void* ptr,
                     uint64_t d0, uint64_t d1, uint64_t d2) {
    cuuint64_t dims[3]    = {d0, d1, d2};
    cuuint64_t strides[2] = {d0 * 2, d0 * d1 * 2};
    cuuint32_t box[3]     = {64, 128, 1};
    cuuint32_t es[3]      = {1, 1, 1};
    enc(tm, CU_TENSOR_MAP_DATA_TYPE_FLOAT16, 3, ptr, dims, strides, box, es,
        CU_TENSOR_MAP_INTERLEAVE_NONE, CU_TENSOR_MAP_SWIZZLE_128B,
        CU_TENSOR_MAP_L2_PROMOTION_L2_128B, CU_TENSOR_MAP_FLOAT_OOB_FILL_NONE);
}

extern "C" void kernel_launch(void* const* d_in, const int* in_sizes, int n_in,
                              void* d_out, int out_size) {
    const float* x      = (const float*)d_in[0];
    const int*   groups = (const int*)d_in[1];   // int32 (JAX demotes int64)
    const float* W1     = (const float*)d_in[2];
    const float* b1     = (const float*)d_in[3];
    const float* W2     = (const float*)d_in[4];
    const float* b2     = (const float*)d_in[5];
    float* out = (float*)d_out;

    constexpr int SMEM_BYTES = 1024 + NS * 65536;  // 197632
    static bool attr_done = false;
    if (!attr_done) {
        cudaFuncSetAttribute(gemm_tc<1>, cudaFuncAttributeMaxDynamicSharedMemorySize, SMEM_BYTES);
        cudaFuncSetAttribute(gemm_tc<2>, cudaFuncAttributeMaxDynamicSharedMemorySize, SMEM_BYTES);
        attr_done = true;
    }

    // resolve driver tensormap encoder through the runtime (no -lcuda needed)
    PFN_tmEncode enc = nullptr;
    cudaDriverEntryPointQueryResult qres;
    cudaGetDriverEntryPoint("cuTensorMapEncodeTiled", (void**)&enc,
                            cudaEnableDefault, &qres);

    __half *xh, *xl, *hh, *hl, *w1h, *w1l, *w2h, *w2l;
    cudaGetSymbolAddress((void**)&xh,  g_x_hi);
    cudaGetSymbolAddress((void**)&xl,  g_x_lo);
    cudaGetSymbolAddress((void**)&hh,  g_h_hi);
    cudaGetSymbolAddress((void**)&hl,  g_h_lo);
    cudaGetSymbolAddress((void**)&w1h, g_w1_hi);
    cudaGetSymbolAddress((void**)&w1l, g_w1_lo);
    cudaGetSymbolAddress((void**)&w2h, g_w2_hi);
    cudaGetSymbolAddress((void**)&w2l, g_w2_lo);

    CUtensorMap tA1h, tA1l, tB1h, tB1l, tA2h, tA2l, tB2h, tB2l;
    make_map(enc, &tA1h, xh,  DIN, NTOK, 1);
    make_map(enc, &tA1l, xl,  DIN, NTOK, 1);
    make_map(enc, &tB1h, w1h, DIN, DH,   NE);
    make_map(enc, &tB1l, w1l, DIN, DH,   NE);
    make_map(enc, &tA2h, hh,  DH,  NTOK, 1);
    make_map(enc, &tA2l, hl,  DH,  NTOK, 1);
    make_map(enc, &tB2h, w2h, DH,  DOUT, NE);
    make_map(enc, &tB2l, w2l, DH,  DOUT, NE);

    // routing (2 launches) + conversion (3) -> gemm1 is launch #6 for ncu -s 5
    k_count<<<1, 256>>>(groups);
    k_scatter<<<(NTOK + 255) / 256, 256>>>(groups);
    k_convert_x<<<(NTOK * DIN / 4) / 256, 256>>>(x);
    k_convert_w<<<dim3(DH / 32, DIN / 32, NE), dim3(32, 8)>>>(W1, w1h, w1l, DIN, DH);
    k_convert_w<<<dim3(DOUT / 32, DH / 32, NE), dim3(32, 8)>>>(W2, w2h, w2l, DH, DOUT);

    gemm_tc<1><<<dim3(DH / 128,  NE * TPE), 128, SMEM_BYTES>>>(tA1h, tA1l, tB1h, tB1l, b1, nullptr);
    gemm_tc<2><<<dim3(DOUT / 128, NE * TPE), 128, SMEM_BYTES>>>(tA2h, tA2l, tB2h, tB2l, b2, out);
}

// round 10
// speedup vs baseline: 6.5287x; 1.0795x over previous
#include <cuda_runtime.h>
#include <cuda_fp16.h>
#include <cuda.h>
#include <cstdint>

#define NTOK 8192
#define DIN  512
#define DH   2048
#define DOUT 512
#define NE   8
#define TPE  64   // max m-tiles (128 rows) per expert
#define NS   2    // pipeline stages
#define NT   256  // n-tile

#if defined(__CUDA_ARCH__) && (__CUDA_ARCH__ >= 1000) && \
    (defined(__CUDA_ARCH_FEAT_SM103_ALL) || defined(__CUDA_ARCH_FEAT_SM100_ALL))
#define TC_OK 1
#else
#define TC_OK 0
#endif

// ---- scratch (__device__ globals: allocation-free rule) ----
__device__ int g_cnt[NE], g_off[NE], g_idx[NTOK];
__device__ __half g_x_hi[(size_t)NTOK * DIN],  g_x_lo[(size_t)NTOK * DIN];    // sorted x
__device__ __half g_h_hi[(size_t)NTOK * DH],   g_h_lo[(size_t)NTOK * DH];     // sorted h
__device__ __half g_w1_hi[(size_t)NE * DH * DIN],  g_w1_lo[(size_t)NE * DH * DIN];   // [e][n][k]
__device__ __half g_w2_hi[(size_t)NE * DOUT * DH], g_w2_lo[(size_t)NE * DOUT * DH];  // [e][n][k]

// ================= helpers =================
__device__ __forceinline__ uint32_t smem_u32(const void* p) {
    uint32_t a;
    asm("{ .reg .u64 t; cvta.to.shared.u64 t, %1; cvt.u32.u64 %0, t; }" : "=r"(a) : "l"(p));
    return a;
}

static constexpr uint64_t DESC_BASE =
    (uint64_t(2) << 61) | (uint64_t(1) << 46) | (uint64_t(64) << 32) | (uint64_t(1) << 16);
__device__ __forceinline__ uint64_t mkdesc(uint32_t addr) {
    return DESC_BASE | ((uint64_t)(addr >> 4) & 0x3FFF);
}

// kind::f16, f32 accum, M=128 (8<<24), N<<17/8
#define MMA_IDESC (0x08000010u | ((NT / 8) << 17))

__device__ __forceinline__ uint32_t pack2(__half a, __half b) {
    __half2 p = __halves2half2(a, b);
    return *reinterpret_cast<uint32_t*>(&p);
}
__device__ __forceinline__ void split(float v, __half& h, __half& l) {
    h = __float2half_rn(v);
    l = __float2half_rn(v - __half2float(h));
}

#if TC_OK
__device__ __forceinline__ void mma_ss(uint32_t d, uint64_t a, uint64_t b, bool acc) {
    uint32_t en = acc ? 1u : 0u;
    asm volatile(
        "{\n\t.reg .pred p;\n\tsetp.ne.u32 p, %4, 0;\n\t"
        "tcgen05.mma.cta_group::1.kind::f16 [%0], %1, %2, %3, {%5,%5,%5,%5}, p;\n\t}"
        :: "r"(d), "l"(a), "l"(b), "r"(MMA_IDESC), "r"(en), "r"(0u) : "memory");
}

#define WAIT_PARITY(mbar, ph) do {                                              \
    uint32_t _m = (mbar), _p = (ph), _d;                                        \
    asm volatile("{\n\t.reg .pred p;\n\t"                                       \
        "mbarrier.try_wait.parity.acquire.cta.shared::cta.b64 p, [%1], %2;\n\t" \
        "selp.b32 %0,1,0,p;\n\t}" : "=r"(_d) : "r"(_m), "r"(_p) : "memory");    \
    if (!_d) {                                                                  \
        asm volatile("{\n\t.reg .pred P1;\n\t"                                  \
            "WL_%=:\n\t"                                                        \
            "mbarrier.try_wait.parity.acquire.cta.shared::cta.b64 P1, [%0], %1, 0x989680;\n\t" \
            "@P1 bra.uni WD_%=;\n\tbra.uni WL_%=;\n\tWD_%=:\n\t}"               \
            :: "r"(_m), "r"(_p) : "memory");                                    \
    }                                                                           \
} while (0)

#define TMA3D(smaddr, tmap, cx, cy, cz, mbar)                                      \
    asm volatile(                                                                  \
        "cp.async.bulk.tensor.3d.shared::cta.global.tile.mbarrier::complete_tx::bytes " \
        "[%0], [%1, {%2, %3, %4}], [%5];"                                          \
        :: "r"(smaddr), "l"(tmap), "r"(cx), "r"(cy), "r"(cz), "r"(mbar) : "memory")

#define LDTM_X32(r, ta)                                                          \
    asm volatile("tcgen05.ld.sync.aligned.32x32b.x32.b32 "                       \
        "{%0,%1,%2,%3,%4,%5,%6,%7,%8,%9,%10,%11,%12,%13,%14,%15,"                \
        "%16,%17,%18,%19,%20,%21,%22,%23,%24,%25,%26,%27,%28,%29,%30,%31}, [%32];" \
        : "=r"((r)[0]),"=r"((r)[1]),"=r"((r)[2]),"=r"((r)[3]),                   \
          "=r"((r)[4]),"=r"((r)[5]),"=r"((r)[6]),"=r"((r)[7]),                   \
          "=r"((r)[8]),"=r"((r)[9]),"=r"((r)[10]),"=r"((r)[11]),                 \
          "=r"((r)[12]),"=r"((r)[13]),"=r"((r)[14]),"=r"((r)[15]),               \
          "=r"((r)[16]),"=r"((r)[17]),"=r"((r)[18]),"=r"((r)[19]),               \
          "=r"((r)[20]),"=r"((r)[21]),"=r"((r)[22]),"=r"((r)[23]),               \
          "=r"((r)[24]),"=r"((r)[25]),"=r"((r)[26]),"=r"((r)[27]),               \
          "=r"((r)[28]),"=r"((r)[29]),"=r"((r)[30]),"=r"((r)[31])                \
        : "r"(ta))
#endif // TC_OK

// ================= routing: ONE kernel (single block) =================
__global__ void __launch_bounds__(1024) k_route(const int* __restrict__ g) {
    __shared__ int c[NE], pos[NE];
    int tid = threadIdx.x;
    if (tid < NE) { c[tid] = 0; }
    __syncthreads();
    #pragma unroll
    for (int i = tid; i < NTOK; i += 1024) atomicAdd(&c[g[i] & (NE - 1)], 1);
    __syncthreads();
    if (tid == 0) {
        int s = 0;
        for (int e = 0; e < NE; e++) { g_off[e] = s; g_cnt[e] = c[e]; pos[e] = s; s += c[e]; }
    }
    __syncthreads();
    #pragma unroll
    for (int i = tid; i < NTOK; i += 1024) {
        int e = g[i] & (NE - 1);
        int p = atomicAdd(&pos[e], 1);
        g_idx[p] = i;
    }
}

// ================= pre-conversion =================
__global__ void __launch_bounds__(256) k_convert_x(const float* __restrict__ x) {
    int i = blockIdx.x * blockDim.x + threadIdx.x;   // 0 .. NTOK*DIN/4-1
    int row = i >> 7;                 // DIN/4 = 128 float4 per row
    int c = (i & 127) * 4;
    int tok = g_idx[row];
    float4 v = *(const float4*)(x + (size_t)tok * DIN + c);
    __half h0,h1,h2,h3,l0,l1,l2,l3;
    split(v.x,h0,l0); split(v.y,h1,l1); split(v.z,h2,l2); split(v.w,h3,l3);
    *(uint2*)(g_x_hi + (size_t)row * DIN + c) = make_uint2(pack2(h0,h1), pack2(h2,h3));
    *(uint2*)(g_x_lo + (size_t)row * DIN + c) = make_uint2(pack2(l0,l1), pack2(l2,l3));
}

// W [e][K][N] fp32 -> Wt hi/lo [e][N][K] fp16 (SMEM 32x32 tile transpose)
__global__ void __launch_bounds__(256) k_convert_w(const float* __restrict__ W,
                                                   __half* __restrict__ Whi,
                                                   __half* __restrict__ Wlo,
                                                   int K, int N) {
    __shared__ float t[32][33];
    int e = blockIdx.z;
    int k0 = blockIdx.y * 32, n0 = blockIdx.x * 32;
    int tx = threadIdx.x, ty = threadIdx.y;   // (32, 8)
    const float* Wb = W + (size_t)e * K * N;
    #pragma unroll
    for (int j = 0; j < 4; j++) {
        int kk = ty + j * 8;
        t[kk][tx] = Wb[(size_t)(k0 + kk) * N + n0 + tx];
    }
    __syncthreads();
    __half* Hb = Whi + ((size_t)e * N + n0) * K + k0;
    __half* Lb = Wlo + ((size_t)e * N + n0) * K + k0;
    #pragma unroll
    for (int j = 0; j < 4; j++) {
        int nn = ty + j * 8;
        float v = t[tx][nn];
        __half h, l; split(v, h, l);
        Hb[(size_t)nn * K + tx] = h;
        Lb[(size_t)nn * K + tx] = l;
    }
}

// ================= tcgen05 fp16-split GEMM, TMA pipeline, N-tile=256 =========
// PHASE 1: h = relu(x_s @ W1t^T + b1)  K=512,  N=2048
// PHASE 2: out = h_s @ W2t^T + b2      K=2048, N=512  (scatter store)
template<int PHASE>
__global__ void __launch_bounds__(128)
gemm_tc(const __grid_constant__ CUtensorMap tmAh,
        const __grid_constant__ CUtensorMap tmAl,
        const __grid_constant__ CUtensorMap tmBh,
        const __grid_constant__ CUtensorMap tmBl,
        const float* __restrict__ bias, float* __restrict__ OUT)
{
#if TC_OK
    constexpr int K = (PHASE == 1) ? DIN : DH;
    constexpr int N = (PHASE == 1) ? DH : DOUT;
    constexpr int NCHUNK = K / 64;
    constexpr uint32_t A_BYTES = 128 * 128;           // 16 KB per half
    constexpr uint32_t B_BYTES = NT * 128;            // 32 KB per half
    constexpr uint32_t STAGE_BYTES = 2 * A_BYTES + 2 * B_BYTES;  // 96 KB
    constexpr uint32_t OFF_AL = A_BYTES, OFF_BH = 2 * A_BYTES, OFF_BL = 2 * A_BYTES + B_BYTES;

    const int e  = blockIdx.y / TPE;
    const int mt = blockIdx.y % TPE;
    const int cnt = g_cnt[e];
    const int m0  = mt * 128;
    if (m0 >= cnt) return;
    const int off = g_off[e];
    const int bn  = blockIdx.x * NT;

    extern __shared__ char smem[];
    const uint32_t sb = smem_u32(smem);
    // header: [0] tmem ptr; full mbars at 8+8s; empty at 32+8s; done at 56
    const int tid = threadIdx.x, wid = tid >> 5;

    if (wid == 0) {
        asm volatile("tcgen05.alloc.cta_group::1.sync.aligned.shared::cta.b32 [%0], %1;"
                     :: "r"(sb), "r"(256u) : "memory");
        asm volatile("tcgen05.relinquish_alloc_permit.cta_group::1.sync.aligned;");
    }
    __syncthreads();
    uint32_t tmem;
    asm volatile("ld.shared.b32 %0,[%1];" : "=r"(tmem) : "r"(sb));
    if (tid == 0) {
        #pragma unroll
        for (int s = 0; s < NS; s++) {
            asm volatile("mbarrier.init.shared.b64 [%0], 1;" :: "r"(sb + 8  + s * 8) : "memory");
            asm volatile("mbarrier.init.shared.b64 [%0], 1;" :: "r"(sb + 32 + s * 8) : "memory");
        }
        asm volatile("mbarrier.init.shared.b64 [%0], 1;" :: "r"(sb + 56) : "memory");
    }
    __syncthreads();

    const int rowA = off + m0;   // OOB rows -> TMA zero fill

    if (tid == 96) {
        // ================= producer: TMA =================
        for (int kc = 0; kc < NCHUNK; kc++) {
            const int s = kc % NS;
            const int r = kc / NS;
            WAIT_PARITY(sb + 32 + s * 8, (r & 1) ^ 1);   // stage free (first pass immediate)
            uint32_t full = sb + 8 + s * 8;
            asm volatile("mbarrier.arrive.expect_tx.shared.b64 _, [%0], %1;"
                         :: "r"(full), "r"(STAGE_BYTES) : "memory");
            uint32_t st = sb + 1024 + (uint32_t)s * STAGE_BYTES;
            int kx = kc * 64;
            TMA3D(st + 0,      &tmAh, kx, rowA, 0, full);
            TMA3D(st + OFF_AL, &tmAl, kx, rowA, 0, full);
            TMA3D(st + OFF_BH, &tmBh, kx, bn,   e, full);
            TMA3D(st + OFF_BL, &tmBl, kx, bn,   e, full);
        }
    } else if (tid == 0) {
        // ================= consumer: MMA =================
        for (int kc = 0; kc < NCHUNK; kc++) {
            const int s = kc % NS;
            const int r = kc / NS;
            WAIT_PARITY(sb + 8 + s * 8, r & 1);          // data ready
            uint32_t st = sb + 1024 + (uint32_t)s * STAGE_BYTES;
            uint64_t dAh = mkdesc(st), dAl = mkdesc(st + OFF_AL);
            uint64_t dBh = mkdesc(st + OFF_BH), dBl = mkdesc(st + OFF_BL);
            #pragma unroll
            for (int ks = 0; ks < 4; ks++) {
                uint64_t oa = (uint64_t)(ks * 2);
                mma_ss(tmem, dAh + oa, dBh + oa, !(kc == 0 && ks == 0));
                mma_ss(tmem, dAh + oa, dBl + oa, true);
                mma_ss(tmem, dAl + oa, dBh + oa, true);
            }
            asm volatile(
                "tcgen05.commit.cta_group::1.mbarrier::arrive::one.shared::cluster.b64 [%0];"
                :: "r"(sb + 32 + s * 8) : "memory");
        }
        asm volatile(
            "tcgen05.commit.cta_group::1.mbarrier::arrive::one.shared::cluster.b64 [%0];"
            :: "r"(sb + 56) : "memory");
    }

    // all threads wait for the final MMA
    WAIT_PARITY(sb + 56, 0);
    asm volatile("tcgen05.fence::after_thread_sync;" ::: "memory");

    // ---- epilogue: thread tid owns output row tid of the tile ----
    const float* bb = bias + (size_t)e * N;
    const bool valid = (m0 + tid) < cnt;
    const int srow = off + m0 + tid;
    #pragma unroll
    for (int cb = 0; cb < NT / 32; cb++) {
        uint32_t d[32];
        LDTM_X32(d, tmem + cb * 32);
        asm volatile("tcgen05.wait::ld.sync.aligned;" ::: "memory");
        if (valid) {
            int n0 = bn + cb * 32;
            if (PHASE == 1) {
                #pragma unroll
                for (int c = 0; c < 32; c += 2) {
                    float v0 = fmaxf(__uint_as_float(d[c])   + __ldg(bb + n0 + c),     0.f);
                    float v1 = fmaxf(__uint_as_float(d[c+1]) + __ldg(bb + n0 + c + 1), 0.f);
                    __half h0,h1,l0,l1;
                    split(v0,h0,l0); split(v1,h1,l1);
                    *(uint32_t*)(g_h_hi + (size_t)srow * DH + n0 + c) = pack2(h0,h1);
                    *(uint32_t*)(g_h_lo + (size_t)srow * DH + n0 + c) = pack2(l0,l1);
                }
            } else {
                int otok = g_idx[srow];
                #pragma unroll
                for (int c = 0; c < 32; c += 4) {
                    float4 v;
                    v.x = __uint_as_float(d[c])   + __ldg(bb + n0 + c);
                    v.y = __uint_as_float(d[c+1]) + __ldg(bb + n0 + c + 1);
                    v.z = __uint_as_float(d[c+2]) + __ldg(bb + n0 + c + 2);
                    v.w = __uint_as_float(d[c+3]) + __ldg(bb + n0 + c + 3);
                    *(float4*)(OUT + (size_t)otok * DOUT + n0 + c) = v;
                }
            }
        }
    }
    asm volatile("tcgen05.fence::before_thread_sync;" ::: "memory");
    __syncthreads();
    if (tid == 0) {
        #pragma unroll
        for (int s = 0; s < NS; s++) {
            asm volatile("mbarrier.inval.shared.b64 [%0];" :: "r"(sb + 8  + s * 8) : "memory");
            asm volatile("mbarrier.inval.shared.b64 [%0];" :: "r"(sb + 32 + s * 8) : "memory");
        }
        asm volatile("mbarrier.inval.shared.b64 [%0];" :: "r"(sb + 56) : "memory");
    }
    __syncthreads();
    if (wid == 0)
        asm volatile("tcgen05.dealloc.cta_group::1.sync.aligned.b32 %0, %1;"
                     :: "r"(tmem), "r"(256u));
#endif // TC_OK
}

// ================= host: tensormap builder =================
typedef CUresult (*PFN_tmEncode)(CUtensorMap*, CUtensorMapDataType, cuuint32_t, void*,
                                 const cuuint64_t*, const cuuint64_t*, const cuuint32_t*,
                                 const cuuint32_t*, CUtensorMapInterleave, CUtensorMapSwizzle,
                                 CUtensorMapL2promotion, CUtensorMapFloatOOBfill);

static void make_map(PFN_tmEncode enc, CUtensorMap* tm, void* ptr,
                     uint64_t d0, uint64_t d1, uint64_t d2, uint32_t box1) {
    cuuint64_t dims[3]    = {d0, d1, d2};
    cuuint64_t strides[2] = {d0 * 2, d0 * d1 * 2};
    cuuint32_t box[3]     = {64, box1, 1};
    cuuint32_t es[3]      = {1, 1, 1};
    enc(tm, CU_TENSOR_MAP_DATA_TYPE_FLOAT16, 3, ptr, dims, strides, box, es,
        CU_TENSOR_MAP_INTERLEAVE_NONE, CU_TENSOR_MAP_SWIZZLE_128B,
        CU_TENSOR_MAP_L2_PROMOTION_L2_128B, CU_TENSOR_MAP_FLOAT_OOB_FILL_NONE);
}

extern "C" void kernel_launch(void* const* d_in, const int* in_sizes, int n_in,
                              void* d_out, int out_size) {
    const float* x      = (const float*)d_in[0];
    const int*   groups = (const int*)d_in[1];   // int32 (JAX demotes int64)
    const float* W1     = (const float*)d_in[2];
    const float* b1     = (const float*)d_in[3];
    const float* W2     = (const float*)d_in[4];
    const float* b2     = (const float*)d_in[5];
    float* out = (float*)d_out;

    constexpr int SMEM_BYTES = 1024 + NS * (2 * 128 * 128 + 2 * NT * 128);  // 197632
    static bool attr_done = false;
    if (!attr_done) {
        cudaFuncSetAttribute(gemm_tc<1>, cudaFuncAttributeMaxDynamicSharedMemorySize, SMEM_BYTES);
        cudaFuncSetAttribute(gemm_tc<2>, cudaFuncAttributeMaxDynamicSharedMemorySize, SMEM_BYTES);
        attr_done = true;
    }

    PFN_tmEncode enc = nullptr;
    cudaDriverEntryPointQueryResult qres;
    cudaGetDriverEntryPoint("cuTensorMapEncodeTiled", (void**)&enc,
                            cudaEnableDefault, &qres);

    __half *xh, *xl, *hh, *hl, *w1h, *w1l, *w2h, *w2l;
    cudaGetSymbolAddress((void**)&xh,  g_x_hi);
    cudaGetSymbolAddress((void**)&xl,  g_x_lo);
    cudaGetSymbolAddress((void**)&hh,  g_h_hi);
    cudaGetSymbolAddress((void**)&hl,  g_h_lo);
    cudaGetSymbolAddress((void**)&w1h, g_w1_hi);
    cudaGetSymbolAddress((void**)&w1l, g_w1_lo);
    cudaGetSymbolAddress((void**)&w2h, g_w2_hi);
    cudaGetSymbolAddress((void**)&w2l, g_w2_lo);

    CUtensorMap tA1h, tA1l, tB1h, tB1l, tA2h, tA2l, tB2h, tB2l;
    make_map(enc, &tA1h, xh,  DIN, NTOK, 1,  128);
    make_map(enc, &tA1l, xl,  DIN, NTOK, 1,  128);
    make_map(enc, &tB1h, w1h, DIN, DH,   NE, NT);
    make_map(enc, &tB1l, w1l, DIN, DH,   NE, NT);
    make_map(enc, &tA2h, hh,  DH,  NTOK, 1,  128);
    make_map(enc, &tA2l, hl,  DH,  NTOK, 1,  128);
    make_map(enc, &tB2h, w2h, DH,  DOUT, NE, NT);
    make_map(enc, &tB2l, w2l, DH,  DOUT, NE, NT);

    // 4 launches before gemm1 so ncu capture slot lands on gemm_tc<1>
    k_route<<<1, 1024>>>(groups);
    k_convert_x<<<(NTOK * DIN / 4) / 256, 256>>>(x);
    k_convert_w<<<dim3(DH / 32, DIN / 32, NE), dim3(32, 8)>>>(W1, w1h, w1l, DIN, DH);
    k_convert_w<<<dim3(DOUT / 32, DH / 32, NE), dim3(32, 8)>>>(W2, w2h, w2l, DH, DOUT);

    gemm_tc<1><<<dim3(DH / NT,   NE * TPE), 128, SMEM_BYTES>>>(tA1h, tA1l, tB1h, tB1l, b1, nullptr);
    gemm_tc<2><<<dim3(DOUT / NT, NE * TPE), 128, SMEM_BYTES>>>(tA2h, tA2l, tB2h, tB2l, b2, out);
}

// round 11
// speedup vs baseline: 12.6432x; 1.9366x over previous
#include <cuda_runtime.h>
#include <cuda_fp16.h>
#include <cuda.h>
#include <cstdint>

#define NTOK 8192
#define DIN  512
#define DH   2048
#define DOUT 512
#define NE   8
#define TPE  64   // max m-tiles (128 rows) per expert
#define NS   2    // pipeline stages
#define NT   256  // n-tile

#if defined(__CUDA_ARCH__) && (__CUDA_ARCH__ >= 1000) && \
    (defined(__CUDA_ARCH_FEAT_SM103_ALL) || defined(__CUDA_ARCH_FEAT_SM100_ALL))
#define TC_OK 1
#else
#define TC_OK 0
#endif

// ---- scratch (__device__ globals: allocation-free rule) ----
__device__ int g_cnt[NE], g_off[NE], g_idx[NTOK];
__device__ __half g_x[(size_t)NTOK * DIN];               // sorted x (fp16)
__device__ __half g_h[(size_t)NTOK * DH];                // sorted h (fp16)
__device__ __half g_w1[(size_t)NE * DH * DIN];           // [e][n][k] fp16
__device__ __half g_w2[(size_t)NE * DOUT * DH];          // [e][n][k] fp16

// ================= helpers =================
__device__ __forceinline__ uint32_t smem_u32(const void* p) {
    uint32_t a;
    asm("{ .reg .u64 t; cvta.to.shared.u64 t, %1; cvt.u32.u64 %0, t; }" : "=r"(a) : "l"(p));
    return a;
}

static constexpr uint64_t DESC_BASE =
    (uint64_t(2) << 61) | (uint64_t(1) << 46) | (uint64_t(64) << 32) | (uint64_t(1) << 16);
__device__ __forceinline__ uint64_t mkdesc(uint32_t addr) {
    return DESC_BASE | ((uint64_t)(addr >> 4) & 0x3FFF);
}

// kind::f16, f32 accum, M=128 (8<<24), N/8<<17
#define MMA_IDESC (0x08000010u | ((NT / 8) << 17))

__device__ __forceinline__ uint32_t pack2(__half a, __half b) {
    __half2 p = __halves2half2(a, b);
    return *reinterpret_cast<uint32_t*>(&p);
}

#if TC_OK
__device__ __forceinline__ void mma_ss(uint32_t d, uint64_t a, uint64_t b, bool acc) {
    uint32_t en = acc ? 1u : 0u;
    asm volatile(
        "{\n\t.reg .pred p;\n\tsetp.ne.u32 p, %4, 0;\n\t"
        "tcgen05.mma.cta_group::1.kind::f16 [%0], %1, %2, %3, {%5,%5,%5,%5}, p;\n\t}"
        :: "r"(d), "l"(a), "l"(b), "r"(MMA_IDESC), "r"(en), "r"(0u) : "memory");
}

#define WAIT_PARITY(mbar, ph) do {                                              \
    uint32_t _m = (mbar), _p = (ph), _d;                                        \
    asm volatile("{\n\t.reg .pred p;\n\t"                                       \
        "mbarrier.try_wait.parity.acquire.cta.shared::cta.b64 p, [%1], %2;\n\t" \
        "selp.b32 %0,1,0,p;\n\t}" : "=r"(_d) : "r"(_m), "r"(_p) : "memory");    \
    if (!_d) {                                                                  \
        asm volatile("{\n\t.reg .pred P1;\n\t"                                  \
            "WL_%=:\n\t"                                                        \
            "mbarrier.try_wait.parity.acquire.cta.shared::cta.b64 P1, [%0], %1, 0x989680;\n\t" \
            "@P1 bra.uni WD_%=;\n\tbra.uni WL_%=;\n\tWD_%=:\n\t}"               \
            :: "r"(_m), "r"(_p) : "memory");                                    \
    }                                                                           \
} while (0)

#define TMA3D(smaddr, tmap, cx, cy, cz, mbar)                                      \
    asm volatile(                                                                  \
        "cp.async.bulk.tensor.3d.shared::cta.global.tile.mbarrier::complete_tx::bytes " \
        "[%0], [%1, {%2, %3, %4}], [%5];"                                          \
        :: "r"(smaddr), "l"(tmap), "r"(cx), "r"(cy), "r"(cz), "r"(mbar) : "memory")

#define LDTM_X32(r, ta)                                                          \
    asm volatile("tcgen05.ld.sync.aligned.32x32b.x32.b32 "                       \
        "{%0,%1,%2,%3,%4,%5,%6,%7,%8,%9,%10,%11,%12,%13,%14,%15,"                \
        "%16,%17,%18,%19,%20,%21,%22,%23,%24,%25,%26,%27,%28,%29,%30,%31}, [%32];" \
        : "=r"((r)[0]),"=r"((r)[1]),"=r"((r)[2]),"=r"((r)[3]),                   \
          "=r"((r)[4]),"=r"((r)[5]),"=r"((r)[6]),"=r"((r)[7]),                   \
          "=r"((r)[8]),"=r"((r)[9]),"=r"((r)[10]),"=r"((r)[11]),                 \
          "=r"((r)[12]),"=r"((r)[13]),"=r"((r)[14]),"=r"((r)[15]),               \
          "=r"((r)[16]),"=r"((r)[17]),"=r"((r)[18]),"=r"((r)[19]),               \
          "=r"((r)[20]),"=r"((r)[21]),"=r"((r)[22]),"=r"((r)[23]),               \
          "=r"((r)[24]),"=r"((r)[25]),"=r"((r)[26]),"=r"((r)[27]),               \
          "=r"((r)[28]),"=r"((r)[29]),"=r"((r)[30]),"=r"((r)[31])                \
        : "r"(ta))
#endif // TC_OK

// ================= routing: ONE kernel (single block) =================
__global__ void __launch_bounds__(1024) k_route(const int* __restrict__ g) {
    __shared__ int c[NE], pos[NE];
    int tid = threadIdx.x;
    if (tid < NE) { c[tid] = 0; }
    __syncthreads();
    #pragma unroll
    for (int i = tid; i < NTOK; i += 1024) atomicAdd(&c[g[i] & (NE - 1)], 1);
    __syncthreads();
    if (tid == 0) {
        int s = 0;
        for (int e = 0; e < NE; e++) { g_off[e] = s; g_cnt[e] = c[e]; pos[e] = s; s += c[e]; }
    }
    __syncthreads();
    #pragma unroll
    for (int i = tid; i < NTOK; i += 1024) {
        int e = g[i] & (NE - 1);
        int p = atomicAdd(&pos[e], 1);
        g_idx[p] = i;
    }
}

// ================= pre-conversion =================
__global__ void __launch_bounds__(256) k_convert_x(const float* __restrict__ x) {
    int i = blockIdx.x * blockDim.x + threadIdx.x;   // 0 .. NTOK*DIN/4-1
    int row = i >> 7;                 // DIN/4 = 128 float4 per row
    int c = (i & 127) * 4;
    int tok = g_idx[row];
    float4 v = *(const float4*)(x + (size_t)tok * DIN + c);
    *(uint2*)(g_x + (size_t)row * DIN + c) =
        make_uint2(pack2(__float2half_rn(v.x), __float2half_rn(v.y)),
                   pack2(__float2half_rn(v.z), __float2half_rn(v.w)));
}

// W [e][K][N] fp32 -> Wt [e][N][K] fp16 (SMEM 32x32 tile transpose)
__global__ void __launch_bounds__(256) k_convert_w(const float* __restrict__ W,
                                                   __half* __restrict__ Wt,
                                                   int K, int N) {
    __shared__ float t[32][33];
    int e = blockIdx.z;
    int k0 = blockIdx.y * 32, n0 = blockIdx.x * 32;
    int tx = threadIdx.x, ty = threadIdx.y;   // (32, 8)
    const float* Wb = W + (size_t)e * K * N;
    #pragma unroll
    for (int j = 0; j < 4; j++) {
        int kk = ty + j * 8;
        t[kk][tx] = Wb[(size_t)(k0 + kk) * N + n0 + tx];
    }
    __syncthreads();
    __half* Tb = Wt + ((size_t)e * N + n0) * K + k0;
    #pragma unroll
    for (int j = 0; j < 4; j++) {
        int nn = ty + j * 8;
        Tb[(size_t)nn * K + tx] = __float2half_rn(t[tx][nn]);
    }
}

// ================= tcgen05 fp16 GEMM, TMA pipeline, 2 CTAs/SM =================
// PHASE 1: h = relu(x_s @ W1t^T + b1)  K=512,  N=2048
// PHASE 2: out = h_s @ W2t^T + b2      K=2048, N=512  (scatter store)
template<int PHASE>
__global__ void __launch_bounds__(128, 2)
gemm_tc(const __grid_constant__ CUtensorMap tmA,
        const __grid_constant__ CUtensorMap tmB,
        const float* __restrict__ bias, float* __restrict__ OUT)
{
#if TC_OK
    constexpr int K = (PHASE == 1) ? DIN : DH;
    constexpr int N = (PHASE == 1) ? DH : DOUT;
    constexpr int NCHUNK = K / 64;
    constexpr uint32_t A_BYTES = 128 * 128;                     // 16 KB
    constexpr uint32_t B_BYTES = NT * 128;                      // 32 KB
    constexpr uint32_t STAGE_BYTES = A_BYTES + B_BYTES;         // 48 KB
    constexpr uint32_t OFF_B = A_BYTES;

    const int e  = blockIdx.y / TPE;
    const int mt = blockIdx.y % TPE;
    const int cnt = g_cnt[e];
    const int m0  = mt * 128;
    if (m0 >= cnt) return;
    const int off = g_off[e];
    const int bn  = blockIdx.x * NT;

    extern __shared__ char smem[];
    const uint32_t sb = smem_u32(smem);
    // header: [0] tmem ptr; full mbars at 8+8s; empty at 32+8s; done at 56
    const int tid = threadIdx.x, wid = tid >> 5;

    if (wid == 0) {
        asm volatile("tcgen05.alloc.cta_group::1.sync.aligned.shared::cta.b32 [%0], %1;"
                     :: "r"(sb), "r"(256u) : "memory");
        asm volatile("tcgen05.relinquish_alloc_permit.cta_group::1.sync.aligned;");
    }
    __syncthreads();
    uint32_t tmem;
    asm volatile("ld.shared.b32 %0,[%1];" : "=r"(tmem) : "r"(sb));
    if (tid == 0) {
        #pragma unroll
        for (int s = 0; s < NS; s++) {
            asm volatile("mbarrier.init.shared.b64 [%0], 1;" :: "r"(sb + 8  + s * 8) : "memory");
            asm volatile("mbarrier.init.shared.b64 [%0], 1;" :: "r"(sb + 32 + s * 8) : "memory");
        }
        asm volatile("mbarrier.init.shared.b64 [%0], 1;" :: "r"(sb + 56) : "memory");
    }
    __syncthreads();

    const int rowA = off + m0;   // OOB rows -> TMA zero fill

    if (tid == 96) {
        // ================= producer: TMA =================
        for (int kc = 0; kc < NCHUNK; kc++) {
            const int s = kc % NS;
            const int r = kc / NS;
            WAIT_PARITY(sb + 32 + s * 8, (r & 1) ^ 1);   // stage free (first pass immediate)
            uint32_t full = sb + 8 + s * 8;
            asm volatile("mbarrier.arrive.expect_tx.shared.b64 _, [%0], %1;"
                         :: "r"(full), "r"(STAGE_BYTES) : "memory");
            uint32_t st = sb + 1024 + (uint32_t)s * STAGE_BYTES;
            int kx = kc * 64;
            TMA3D(st + 0,     &tmA, kx, rowA, 0, full);
            TMA3D(st + OFF_B, &tmB, kx, bn,   e, full);
        }
    } else if (tid == 0) {
        // ================= consumer: MMA =================
        for (int kc = 0; kc < NCHUNK; kc++) {
            const int s = kc % NS;
            const int r = kc / NS;
            WAIT_PARITY(sb + 8 + s * 8, r & 1);          // data ready
            uint32_t st = sb + 1024 + (uint32_t)s * STAGE_BYTES;
            uint64_t dA = mkdesc(st), dB = mkdesc(st + OFF_B);
            #pragma unroll
            for (int ks = 0; ks < 4; ks++) {
                uint64_t oa = (uint64_t)(ks * 2);
                mma_ss(tmem, dA + oa, dB + oa, !(kc == 0 && ks == 0));
            }
            asm volatile(
                "tcgen05.commit.cta_group::1.mbarrier::arrive::one.shared::cluster.b64 [%0];"
                :: "r"(sb + 32 + s * 8) : "memory");
        }
        asm volatile(
            "tcgen05.commit.cta_group::1.mbarrier::arrive::one.shared::cluster.b64 [%0];"
            :: "r"(sb + 56) : "memory");
    }

    // all threads wait for the final MMA
    WAIT_PARITY(sb + 56, 0);
    asm volatile("tcgen05.fence::after_thread_sync;" ::: "memory");

    // ---- epilogue: thread tid owns output row tid of the tile ----
    const float* bb = bias + (size_t)e * N;
    const bool valid = (m0 + tid) < cnt;
    const int srow = off + m0 + tid;
    #pragma unroll
    for (int cb = 0; cb < NT / 32; cb++) {
        uint32_t d[32];
        LDTM_X32(d, tmem + cb * 32);
        asm volatile("tcgen05.wait::ld.sync.aligned;" ::: "memory");
        if (valid) {
            int n0 = bn + cb * 32;
            if (PHASE == 1) {
                #pragma unroll
                for (int c = 0; c < 32; c += 8) {
                    __half h[8];
                    #pragma unroll
                    for (int j = 0; j < 8; j++)
                        h[j] = __float2half_rn(
                            fmaxf(__uint_as_float(d[c + j]) + __ldg(bb + n0 + c + j), 0.f));
                    *(uint4*)(g_h + (size_t)srow * DH + n0 + c) =
                        make_uint4(pack2(h[0], h[1]), pack2(h[2], h[3]),
                                   pack2(h[4], h[5]), pack2(h[6], h[7]));
                }
            } else {
                int otok = g_idx[srow];
                #pragma unroll
                for (int c = 0; c < 32; c += 4) {
                    float4 v;
                    v.x = __uint_as_float(d[c])   + __ldg(bb + n0 + c);
                    v.y = __uint_as_float(d[c+1]) + __ldg(bb + n0 + c + 1);
                    v.z = __uint_as_float(d[c+2]) + __ldg(bb + n0 + c + 2);
                    v.w = __uint_as_float(d[c+3]) + __ldg(bb + n0 + c + 3);
                    *(float4*)(OUT + (size_t)otok * DOUT + n0 + c) = v;
                }
            }
        }
    }
    asm volatile("tcgen05.fence::before_thread_sync;" ::: "memory");
    __syncthreads();
    if (tid == 0) {
        #pragma unroll
        for (int s = 0; s < NS; s++) {
            asm volatile("mbarrier.inval.shared.b64 [%0];" :: "r"(sb + 8  + s * 8) : "memory");
            asm volatile("mbarrier.inval.shared.b64 [%0];" :: "r"(sb + 32 + s * 8) : "memory");
        }
        asm volatile("mbarrier.inval.shared.b64 [%0];" :: "r"(sb + 56) : "memory");
    }
    __syncthreads();
    if (wid == 0)
        asm volatile("tcgen05.dealloc.cta_group::1.sync.aligned.b32 %0, %1;"
                     :: "r"(tmem), "r"(256u));
#endif // TC_OK
}

// ================= host: tensormap builder =================
typedef CUresult (*PFN_tmEncode)(CUtensorMap*, CUtensorMapDataType, cuuint32_t, void*,
                                 const cuuint64_t*, const cuuint64_t*, const cuuint32_t*,
                                 const cuuint32_t*, CUtensorMapInterleave, CUtensorMapSwizzle,
                                 CUtensorMapL2promotion, CUtensorMapFloatOOBfill);

static void make_map(PFN_tmEncode enc, CUtensorMap* tm, void* ptr,
                     uint64_t d0, uint64_t d1, uint64_t d2, uint32_t box1) {
    cuuint64_t dims[3]    = {d0, d1, d2};
    cuuint64_t strides[2] = {d0 * 2, d0 * d1 * 2};
    cuuint32_t box[3]     = {64, box1, 1};
    cuuint32_t es[3]      = {1, 1, 1};
    enc(tm, CU_TENSOR_MAP_DATA_TYPE_FLOAT16, 3, ptr, dims, strides, box, es,
        CU_TENSOR_MAP_INTERLEAVE_NONE, CU_TENSOR_MAP_SWIZZLE_128B,
        CU_TENSOR_MAP_L2_PROMOTION_L2_128B, CU_TENSOR_MAP_FLOAT_OOB_FILL_NONE);
}

extern "C" void kernel_launch(void* const* d_in, const int* in_sizes, int n_in,
                              void* d_out, int out_size) {
    const float* x      = (const float*)d_in[0];
    const int*   groups = (const int*)d_in[1];   // int32 (JAX demotes int64)
    const float* W1     = (const float*)d_in[2];
    const float* b1     = (const float*)d_in[3];
    const float* W2     = (const float*)d_in[4];
    const float* b2     = (const float*)d_in[5];
    float* out = (float*)d_out;

    constexpr int SMEM_BYTES = 1024 + NS * (128 * 128 + NT * 128);  // 99328 -> 2 CTAs/SM
    static bool attr_done = false;
    if (!attr_done) {
        cudaFuncSetAttribute(gemm_tc<1>, cudaFuncAttributeMaxDynamicSharedMemorySize, SMEM_BYTES);
        cudaFuncSetAttribute(gemm_tc<2>, cudaFuncAttributeMaxDynamicSharedMemorySize, SMEM_BYTES);
        attr_done = true;
    }

    PFN_tmEncode enc = nullptr;
    cudaDriverEntryPointQueryResult qres;
    cudaGetDriverEntryPoint("cuTensorMapEncodeTiled", (void**)&enc,
                            cudaEnableDefault, &qres);

    __half *xp, *hp, *w1p, *w2p;
    cudaGetSymbolAddress((void**)&xp,  g_x);
    cudaGetSymbolAddress((void**)&hp,  g_h);
    cudaGetSymbolAddress((void**)&w1p, g_w1);
    cudaGetSymbolAddress((void**)&w2p, g_w2);

    CUtensorMap tA1, tB1, tA2, tB2;
    make_map(enc, &tA1, xp,  DIN, NTOK, 1,  128);
    make_map(enc, &tB1, w1p, DIN, DH,   NE, NT);
    make_map(enc, &tA2, hp,  DH,  NTOK, 1,  128);
    make_map(enc, &tB2, w2p, DH,  DOUT, NE, NT);

    k_route<<<1, 1024>>>(groups);
    k_convert_x<<<(NTOK * DIN / 4) / 256, 256>>>(x);
    k_convert_w<<<dim3(DH / 32, DIN / 32, NE), dim3(32, 8)>>>(W1, w1p, DIN, DH);
    k_convert_w<<<dim3(DOUT / 32, DH / 32, NE), dim3(32, 8)>>>(W2, w2p, DH, DOUT);

    gemm_tc<1><<<dim3(DH / NT,   NE * TPE), 128, SMEM_BYTES>>>(tA1, tB1, b1, nullptr);
    gemm_tc<2><<<dim3(DOUT / NT, NE * TPE), 128, SMEM_BYTES>>>(tA2, tB2, b2, out);
}